// round 2
// baseline (speedup 1.0000x reference)
#include <cuda_runtime.h>
#include <cuda_bf16.h>
#include <math.h>

#define Bk 4
#define Tk 2048
#define Ck 1024
#define Hk 16
#define HSk 64
#define EPSk 1e-5f
#define MROWS (Bk*Tk)          // 8192
#define N3 (3*Ck)              // 3072
#define FF (4*Ck)              // 4096

// ---------------- scratch (device globals: no allocation allowed) ----------
__device__ float g_h1[MROWS*Ck];        // 32MB
__device__ float g_qkv[MROWS*N3];       // 96MB
__device__ float g_att[MROWS*Ck];       // 32MB
__device__ float g_x2[MROWS*Ck];        // 32MB
__device__ float g_h2[MROWS*Ck];        // 32MB
__device__ float g_ffn[(size_t)MROWS*FF]; // 128MB
__device__ float g_wpack[Ck*N3];        // 12MB
__device__ float g_bpack[N3];

// ---------------- LayerNorm over TIME axis (per (b,c) column) --------------
__global__ void ln_time_kernel(const float* __restrict__ x,
                               const float* __restrict__ g,
                               const float* __restrict__ beta,
                               float* __restrict__ out) {
    // grid: B*(C/32) blocks, block (32,8)
    int cb = blockIdx.x % (Ck/32);
    int b  = blockIdx.x / (Ck/32);
    int tx = threadIdx.x, ty = threadIdx.y;
    int c  = cb*32 + tx;
    const float* xp = x + (size_t)b*Tk*Ck + c;
    float s = 0.f, s2 = 0.f;
    for (int t = ty; t < Tk; t += 8) {
        float v = xp[(size_t)t*Ck];
        s += v; s2 += v*v;
    }
    __shared__ float ss[8][32], ss2[8][32];
    ss[ty][tx] = s; ss2[ty][tx] = s2;
    __syncthreads();
    if (ty == 0) {
        for (int i = 1; i < 8; i++) { s += ss[i][tx]; s2 += ss2[i][tx]; }
        float m   = s / (float)Tk;
        float var = (s2 - (float)Tk*m*m) / (float)(Tk-1);
        float inv = rsqrtf(var + EPSk);
        ss[0][tx]  = m;
        ss2[0][tx] = inv;
    }
    __syncthreads();
    float m = ss[0][tx], inv = ss2[0][tx];
    float gg = g[c], bb = beta[c];
    float* op = out + (size_t)b*Tk*Ck + c;
    for (int t = ty; t < Tk; t += 8) {
        op[(size_t)t*Ck] = gg * (xp[(size_t)t*Ck] - m) * inv + bb;
    }
}

// ---------------- pack [H,C,HS] qkv weights into [C, 3C] -------------------
__global__ void pack_qkv_kernel(const float* __restrict__ Wq, const float* __restrict__ Wk,
                                const float* __restrict__ Wv, const float* __restrict__ bq,
                                const float* __restrict__ bk, const float* __restrict__ bv) {
    int i = blockIdx.x * blockDim.x + threadIdx.x;
    if (i < Ck*Ck) {
        int c = i / Ck;
        int n = i % Ck;            // n = h*HS + d
        int h = n / HSk, d = n % HSk;
        size_t src = (size_t)h*Ck*HSk + (size_t)c*HSk + d;
        g_wpack[(size_t)c*N3 + n]          = Wq[src];
        g_wpack[(size_t)c*N3 + Ck + n]     = Wk[src];
        g_wpack[(size_t)c*N3 + 2*Ck + n]   = Wv[src];
    }
    if (i < Ck) {
        g_bpack[i]        = bq[i];   // [H,HS] flattens exactly to h*64+d
        g_bpack[Ck + i]   = bk[i];
        g_bpack[2*Ck + i] = bv[i];
    }
}

// ---------------- tiled fp32 GEMM: C = A[M,K]@B[K,N] + bias (+res)(+relu) --
template<bool RELU, bool RES>
__global__ void sgemm_kernel(int M, int N, int K,
                             const float* __restrict__ A,
                             const float* __restrict__ Bm,
                             const float* __restrict__ bias,
                             const float* __restrict__ res,
                             float* __restrict__ Cm) {
    const int BM = 128, BN = 128, BK = 16;
    __shared__ float As[BK][BM];
    __shared__ float Bs[BK][BN];
    int tid = threadIdx.x;
    int bm0 = blockIdx.y * BM;
    int bn0 = blockIdx.x * BN;
    int arow = tid / 4;
    int acol = (tid % 4) * 4;
    int brow = tid / 32;
    int bcol = (tid % 32) * 4;
    int ty = tid / 16, tx = tid % 16;
    float acc[8][8];
    #pragma unroll
    for (int i = 0; i < 8; i++)
        #pragma unroll
        for (int j = 0; j < 8; j++) acc[i][j] = 0.f;

    const float* Aptr = A + (size_t)bm0 * K;
    const float* Bptr = Bm + bn0;

    for (int k0 = 0; k0 < K; k0 += BK) {
        #pragma unroll
        for (int i = 0; i < 2; i++) {
            float4 av = *(const float4*)(Aptr + (size_t)(arow + i*64)*K + k0 + acol);
            As[acol+0][arow + i*64] = av.x;
            As[acol+1][arow + i*64] = av.y;
            As[acol+2][arow + i*64] = av.z;
            As[acol+3][arow + i*64] = av.w;
        }
        #pragma unroll
        for (int i = 0; i < 2; i++) {
            *(float4*)&Bs[brow + i*8][bcol] =
                *(const float4*)(Bptr + (size_t)(k0 + brow + i*8)*N + bcol);
        }
        __syncthreads();
        #pragma unroll
        for (int k = 0; k < BK; k++) {
            float4 a0 = *(const float4*)&As[k][ty*8];
            float4 a1 = *(const float4*)&As[k][ty*8 + 4];
            float4 b0 = *(const float4*)&Bs[k][tx*8];
            float4 b1 = *(const float4*)&Bs[k][tx*8 + 4];
            float ra[8] = {a0.x,a0.y,a0.z,a0.w,a1.x,a1.y,a1.z,a1.w};
            float rb[8] = {b0.x,b0.y,b0.z,b0.w,b1.x,b1.y,b1.z,b1.w};
            #pragma unroll
            for (int i = 0; i < 8; i++)
                #pragma unroll
                for (int j = 0; j < 8; j++)
                    acc[i][j] += ra[i] * rb[j];
        }
        __syncthreads();
    }
    #pragma unroll
    for (int i = 0; i < 8; i++) {
        int m = bm0 + ty*8 + i;
        #pragma unroll
        for (int j = 0; j < 8; j++) {
            int n = bn0 + tx*8 + j;
            float v = acc[i][j] + bias[n];
            if (RES)  v += res[(size_t)m*N + n];
            if (RELU) v = fmaxf(v, 0.f);
            Cm[(size_t)m*N + n] = v;
        }
    }
}

// ---------------- flash attention (causal, fp32, 64x64 tiles) --------------
#define FPITCH 68
__global__ void flash_attn_kernel(const float* __restrict__ qkv, float* __restrict__ att) {
    extern __shared__ float sm[];
    float* Qs = sm;
    float* Ks = Qs + 64*FPITCH;
    float* Vs = Ks + 64*FPITCH;
    float* Ps = Vs + 64*FPITCH;
    int tid = threadIdx.x;
    const int ntiles = Tk / 64;  // 32
    int qt = blockIdx.x % ntiles;
    int h  = (blockIdx.x / ntiles) % Hk;
    int b  =  blockIdx.x / (ntiles * Hk);
    int q0 = qt * 64;
    const float* qbase = qkv + (size_t)b*Tk*N3 + h*HSk;
    const float* kbase = qbase + Ck;
    const float* vbase = qbase + 2*Ck;

    for (int i = tid; i < 64*16; i += 256) {
        int r = i / 16, c4 = (i % 16) * 4;
        *(float4*)&Qs[r*FPITCH + c4] = *(const float4*)(qbase + (size_t)(q0 + r)*N3 + c4);
    }
    int r  = tid / 4;
    int cg = tid % 4;
    float mprev = -1e30f, l = 0.f;
    float o[16];
    #pragma unroll
    for (int i = 0; i < 16; i++) o[i] = 0.f;
    int nkb = q0/64 + 1;
    __syncthreads();

    for (int kb = 0; kb < nkb; kb++) {
        for (int i = tid; i < 64*16; i += 256) {
            int rr = i / 16, c4 = (i % 16) * 4;
            *(float4*)&Ks[rr*FPITCH + c4] = *(const float4*)(kbase + (size_t)(kb*64 + rr)*N3 + c4);
            *(float4*)&Vs[rr*FPITCH + c4] = *(const float4*)(vbase + (size_t)(kb*64 + rr)*N3 + c4);
        }
        __syncthreads();
        float s[16];
        #pragma unroll
        for (int jj = 0; jj < 16; jj++) s[jj] = 0.f;
        #pragma unroll 8
        for (int d = 0; d < 64; d++) {
            float qv = Qs[r*FPITCH + d];
            #pragma unroll
            for (int jj = 0; jj < 16; jj++)
                s[jj] += qv * Ks[(jj*4 + cg)*FPITCH + d];
        }
        int qg = q0 + r;
        float smax = -1e30f;
        #pragma unroll
        for (int jj = 0; jj < 16; jj++) {
            int kg = kb*64 + jj*4 + cg;
            s[jj] = (kg <= qg) ? s[jj] * 0.03125f : -1e30f;
            smax = fmaxf(smax, s[jj]);
        }
        smax = fmaxf(smax, __shfl_xor_sync(0xffffffffu, smax, 1));
        smax = fmaxf(smax, __shfl_xor_sync(0xffffffffu, smax, 2));
        float mnew = fmaxf(mprev, smax);
        float corr = __expf(mprev - mnew);
        float psum = 0.f;
        #pragma unroll
        for (int jj = 0; jj < 16; jj++) {
            float p = __expf(s[jj] - mnew);
            Ps[r*FPITCH + jj*4 + cg] = p;
            psum += p;
        }
        psum += __shfl_xor_sync(0xffffffffu, psum, 1);
        psum += __shfl_xor_sync(0xffffffffu, psum, 2);
        l = l * corr + psum;
        mprev = mnew;
        #pragma unroll
        for (int i = 0; i < 16; i++) o[i] *= corr;
        __syncthreads();
        #pragma unroll 8
        for (int j = 0; j < 64; j++) {
            float p = Ps[r*FPITCH + j];
            #pragma unroll
            for (int dd = 0; dd < 16; dd++)
                o[dd] += p * Vs[j*FPITCH + dd*4 + cg];
        }
        __syncthreads();
    }
    float invl = 1.f / l;
    float* ob = att + (size_t)(b*Tk + q0 + r)*Ck + h*HSk;
    #pragma unroll
    for (int dd = 0; dd < 16; dd++)
        ob[dd*4 + cg] = o[dd] * invl;
}

// ---------------------------------------------------------------------------
extern "C" void kernel_launch(void* const* d_in, const int* in_sizes, int n_in,
                              void* d_out, int out_size) {
    const float* x     = (const float*)d_in[0];
    const float* ln1_g = (const float*)d_in[1];
    const float* ln1_b = (const float*)d_in[2];
    const float* ln2_g = (const float*)d_in[3];
    const float* ln2_b = (const float*)d_in[4];
    const float* Wq    = (const float*)d_in[5];
    const float* bq    = (const float*)d_in[6];
    const float* Wk    = (const float*)d_in[7];
    const float* bk    = (const float*)d_in[8];
    const float* Wv    = (const float*)d_in[9];
    const float* bv    = (const float*)d_in[10];
    const float* Wo    = (const float*)d_in[11];
    const float* bo    = (const float*)d_in[12];
    const float* W1    = (const float*)d_in[13];
    const float* b1    = (const float*)d_in[14];
    const float* W2    = (const float*)d_in[15];
    const float* b2    = (const float*)d_in[16];
    float* out = (float*)d_out;

    float *h1, *qkv, *att, *x2, *h2, *ffn, *wpack, *bpack;
    cudaGetSymbolAddress((void**)&h1,    g_h1);
    cudaGetSymbolAddress((void**)&qkv,   g_qkv);
    cudaGetSymbolAddress((void**)&att,   g_att);
    cudaGetSymbolAddress((void**)&x2,    g_x2);
    cudaGetSymbolAddress((void**)&h2,    g_h2);
    cudaGetSymbolAddress((void**)&ffn,   g_ffn);
    cudaGetSymbolAddress((void**)&wpack, g_wpack);
    cudaGetSymbolAddress((void**)&bpack, g_bpack);

    // 1) pack qkv weights/biases
    pack_qkv_kernel<<<(Ck*Ck + 255)/256, 256>>>(Wq, Wk, Wv, bq, bk, bv);

    // 2) ln1(x) -> h1
    dim3 lnb(32, 8);
    ln_time_kernel<<<Bk*(Ck/32), lnb>>>(x, ln1_g, ln1_b, h1);

    // 3) qkv = h1 @ wpack + bpack   [8192 x 3072]
    sgemm_kernel<false,false><<<dim3(N3/128, MROWS/128), 256>>>(
        MROWS, N3, Ck, h1, wpack, bpack, nullptr, qkv);

    // 4) attention -> att [8192 x 1024]
    int fsm = 4*64*FPITCH*sizeof(float);
    cudaFuncSetAttribute(flash_attn_kernel, cudaFuncAttributeMaxDynamicSharedMemorySize, fsm);
    flash_attn_kernel<<<Bk*Hk*(Tk/64), 256, fsm>>>(qkv, att);

    // 5) x2 = x + att @ Wo + bo
    sgemm_kernel<false,true><<<dim3(Ck/128, MROWS/128), 256>>>(
        MROWS, Ck, Ck, att, Wo, bo, x, x2);

    // 6) ln2(x2) -> h2
    ln_time_kernel<<<Bk*(Ck/32), lnb>>>(x2, ln2_g, ln2_b, h2);

    // 7) ffn = relu(h2 @ W1 + b1)  [8192 x 4096]
    sgemm_kernel<true,false><<<dim3(FF/128, MROWS/128), 256>>>(
        MROWS, FF, Ck, h2, W1, b1, nullptr, ffn);

    // 8) out = x2 + ffn @ W2 + b2
    sgemm_kernel<false,true><<<dim3(Ck/128, MROWS/128), 256>>>(
        MROWS, Ck, FF, ffn, W2, b2, x2, out);
}

// round 3
// speedup vs baseline: 1.8224x; 1.8224x over previous
#include <cuda_runtime.h>
#include <cuda_bf16.h>
#include <math.h>

#define Bk 4
#define Tk 2048
#define Ck 1024
#define Hk 16
#define HSk 64
#define EPSk 1e-5f
#define MROWS (Bk*Tk)          // 8192
#define N3 (3*Ck)              // 3072
#define FF (4*Ck)              // 4096

// ---------------- scratch (device globals: no allocation allowed) ----------
__device__ float g_h1[MROWS*Ck];        // 32MB
__device__ float g_qkv[MROWS*N3];       // 96MB
__device__ float g_att[MROWS*Ck];       // 32MB
__device__ float g_x2[MROWS*Ck];        // 32MB
__device__ float g_h2[MROWS*Ck];        // 32MB
__device__ float g_ffn[(size_t)MROWS*FF]; // 128MB
__device__ float g_wpack[Ck*N3];        // 12MB
__device__ float g_bpack[N3];

// ---------------- helpers ---------------------------------------------------
__device__ __forceinline__ void cp_async16(void* s, const void* g) {
    unsigned sa = (unsigned)__cvta_generic_to_shared(s);
    asm volatile("cp.async.cg.shared.global [%0], [%1], 16;\n" :: "r"(sa), "l"(g));
}
__device__ __forceinline__ void cp_commit() { asm volatile("cp.async.commit_group;\n"); }
__device__ __forceinline__ void cp_wait0()  { asm volatile("cp.async.wait_group 0;\n"); }

__device__ __forceinline__ unsigned f2tf(float f) {
    unsigned u;
    asm("cvt.rna.tf32.f32 %0, %1;" : "=r"(u) : "f"(f));
    return u;
}
__device__ __forceinline__ void mma1688(float* c, const unsigned* a, const unsigned* b) {
    asm volatile("mma.sync.aligned.m16n8k8.row.col.f32.tf32.tf32.f32 "
        "{%0,%1,%2,%3}, {%4,%5,%6,%7}, {%8,%9}, {%0,%1,%2,%3};"
        : "+f"(c[0]), "+f"(c[1]), "+f"(c[2]), "+f"(c[3])
        : "r"(a[0]), "r"(a[1]), "r"(a[2]), "r"(a[3]), "r"(b[0]), "r"(b[1]));
}

// ---------------- LayerNorm over TIME axis (per (b,c) column) --------------
__global__ void ln_time_kernel(const float* __restrict__ x,
                               const float* __restrict__ g,
                               const float* __restrict__ beta,
                               float* __restrict__ out) {
    int cb = blockIdx.x % (Ck/32);
    int b  = blockIdx.x / (Ck/32);
    int tx = threadIdx.x, ty = threadIdx.y;
    int c  = cb*32 + tx;
    const float* xp = x + (size_t)b*Tk*Ck + c;
    float s = 0.f, s2 = 0.f;
    for (int t = ty; t < Tk; t += 8) {
        float v = xp[(size_t)t*Ck];
        s += v; s2 += v*v;
    }
    __shared__ float ss[8][32], ss2[8][32];
    ss[ty][tx] = s; ss2[ty][tx] = s2;
    __syncthreads();
    if (ty == 0) {
        for (int i = 1; i < 8; i++) { s += ss[i][tx]; s2 += ss2[i][tx]; }
        float m   = s / (float)Tk;
        float var = (s2 - (float)Tk*m*m) / (float)(Tk-1);
        float inv = rsqrtf(var + EPSk);
        ss[0][tx]  = m;
        ss2[0][tx] = inv;
    }
    __syncthreads();
    float m = ss[0][tx], inv = ss2[0][tx];
    float gg = g[c], bb = beta[c];
    float* op = out + (size_t)b*Tk*Ck + c;
    for (int t = ty; t < Tk; t += 8) {
        op[(size_t)t*Ck] = gg * (xp[(size_t)t*Ck] - m) * inv + bb;
    }
}

// ---------------- pack [H,C,HS] qkv weights into [C, 3C] -------------------
__global__ void pack_qkv_kernel(const float* __restrict__ Wq, const float* __restrict__ Wk,
                                const float* __restrict__ Wv, const float* __restrict__ bq,
                                const float* __restrict__ bk, const float* __restrict__ bv) {
    int i = blockIdx.x * blockDim.x + threadIdx.x;
    if (i < Ck*Ck) {
        int c = i / Ck;
        int n = i % Ck;            // n = h*HS + d
        int h = n / HSk, d = n % HSk;
        size_t src = (size_t)h*Ck*HSk + (size_t)c*HSk + d;
        g_wpack[(size_t)c*N3 + n]          = Wq[src];
        g_wpack[(size_t)c*N3 + Ck + n]     = Wk[src];
        g_wpack[(size_t)c*N3 + 2*Ck + n]   = Wv[src];
    }
    if (i < Ck) {
        g_bpack[i]        = bq[i];
        g_bpack[Ck + i]   = bk[i];
        g_bpack[2*Ck + i] = bv[i];
    }
}

// ---------------- tf32 tensor-core GEMM ------------------------------------
// C = A[M,K] @ B[K,N] + bias (+res)(+relu); all dims multiples of 128/32.
#define APITCH 36
#define BPITCH 136
#define TG_SMEM (2*128*APITCH*4 + 2*32*BPITCH*4)

template<bool RELU, bool RES>
__global__ void tgemm_kernel(int M, int N, int K,
                             const float* __restrict__ A,
                             const float* __restrict__ Bm,
                             const float* __restrict__ bias,
                             const float* __restrict__ res,
                             float* __restrict__ Cm) {
    extern __shared__ float smem[];
    float* As = smem;                     // [2][128][APITCH]
    float* Bs = smem + 2*128*APITCH;      // [2][32][BPITCH]
    int tid  = threadIdx.x;
    int lane = tid & 31, warp = tid >> 5;
    int warpM = warp & 1, warpN = warp >> 1;   // 2 x 4 warps -> 64x32 per warp
    int bm0 = blockIdx.y * 128, bn0 = blockIdx.x * 128;

    float acc[4][4][4];
    #pragma unroll
    for (int a = 0; a < 4; a++)
        #pragma unroll
        for (int b = 0; b < 4; b++)
            #pragma unroll
            for (int c = 0; c < 4; c++) acc[a][b][c] = 0.f;

    auto load_tiles = [&](int k0, int buf) {
        float* ad = As + buf*128*APITCH;
        #pragma unroll
        for (int i = 0; i < 4; i++) {
            int id = tid + i*256;
            int row = id >> 3, cc = (id & 7) << 2;
            cp_async16(ad + row*APITCH + cc, A + (size_t)(bm0+row)*K + k0 + cc);
        }
        float* bd = Bs + buf*32*BPITCH;
        #pragma unroll
        for (int i = 0; i < 4; i++) {
            int id = tid + i*256;
            int row = id >> 5, cc = (id & 31) << 2;
            cp_async16(bd + row*BPITCH + cc, Bm + (size_t)(k0+row)*N + bn0 + cc);
        }
    };

    load_tiles(0, 0);
    cp_commit();
    int nk = K / 32;
    for (int t = 0; t < nk; t++) {
        cp_wait0();
        __syncthreads();
        if (t + 1 < nk) { load_tiles((t+1)*32, (t+1) & 1); cp_commit(); }
        const float* Ab = As + (t & 1)*128*APITCH;
        const float* Bb = Bs + (t & 1)*32*BPITCH;
        #pragma unroll
        for (int kk = 0; kk < 4; kk++) {
            int kc = kk * 8;
            unsigned af[4][4], bf[4][2];
            #pragma unroll
            for (int mt = 0; mt < 4; mt++) {
                int r0 = warpM*64 + mt*16 + (lane >> 2);
                int c0 = kc + (lane & 3);
                af[mt][0] = f2tf(Ab[r0*APITCH + c0]);
                af[mt][1] = f2tf(Ab[(r0+8)*APITCH + c0]);
                af[mt][2] = f2tf(Ab[r0*APITCH + c0 + 4]);
                af[mt][3] = f2tf(Ab[(r0+8)*APITCH + c0 + 4]);
            }
            #pragma unroll
            for (int nt = 0; nt < 4; nt++) {
                int kr = kc + (lane & 3);
                int nc = warpN*32 + nt*8 + (lane >> 2);
                bf[nt][0] = f2tf(Bb[kr*BPITCH + nc]);
                bf[nt][1] = f2tf(Bb[(kr+4)*BPITCH + nc]);
            }
            #pragma unroll
            for (int mt = 0; mt < 4; mt++)
                #pragma unroll
                for (int nt = 0; nt < 4; nt++)
                    mma1688(acc[mt][nt], af[mt], bf[nt]);
        }
        __syncthreads();
    }

    // epilogue
    #pragma unroll
    for (int mt = 0; mt < 4; mt++) {
        #pragma unroll
        for (int nt = 0; nt < 4; nt++) {
            #pragma unroll
            for (int half = 0; half < 2; half++) {
                int row = bm0 + warpM*64 + mt*16 + (lane >> 2) + half*8;
                int col = bn0 + warpN*32 + nt*8 + 2*(lane & 3);
                float v0 = acc[mt][nt][half*2+0] + bias[col];
                float v1 = acc[mt][nt][half*2+1] + bias[col+1];
                if (RES) {
                    v0 += res[(size_t)row*N + col];
                    v1 += res[(size_t)row*N + col + 1];
                }
                if (RELU) { v0 = fmaxf(v0, 0.f); v1 = fmaxf(v1, 0.f); }
                *(float2*)&Cm[(size_t)row*N + col] = make_float2(v0, v1);
            }
        }
    }
}

// ---------------- flash attention (causal, fp32, 64x64 tiles) --------------
#define FPITCH 68
__global__ void flash_attn_kernel(const float* __restrict__ qkv, float* __restrict__ att) {
    extern __shared__ float sm[];
    float* Qs = sm;
    float* Ks = Qs + 64*FPITCH;
    float* Vs = Ks + 64*FPITCH;
    float* Ps = Vs + 64*FPITCH;
    int tid = threadIdx.x;
    const int ntiles = Tk / 64;  // 32
    int qt = blockIdx.x % ntiles;
    int h  = (blockIdx.x / ntiles) % Hk;
    int b  =  blockIdx.x / (ntiles * Hk);
    int q0 = qt * 64;
    const float* qbase = qkv + (size_t)b*Tk*N3 + h*HSk;
    const float* kbase = qbase + Ck;
    const float* vbase = qbase + 2*Ck;

    for (int i = tid; i < 64*16; i += 256) {
        int r = i / 16, c4 = (i % 16) * 4;
        *(float4*)&Qs[r*FPITCH + c4] = *(const float4*)(qbase + (size_t)(q0 + r)*N3 + c4);
    }
    int r  = tid / 4;
    int cg = tid % 4;
    float mprev = -1e30f, l = 0.f;
    float o[16];
    #pragma unroll
    for (int i = 0; i < 16; i++) o[i] = 0.f;
    int nkb = q0/64 + 1;
    __syncthreads();

    for (int kb = 0; kb < nkb; kb++) {
        for (int i = tid; i < 64*16; i += 256) {
            int rr = i / 16, c4 = (i % 16) * 4;
            *(float4*)&Ks[rr*FPITCH + c4] = *(const float4*)(kbase + (size_t)(kb*64 + rr)*N3 + c4);
            *(float4*)&Vs[rr*FPITCH + c4] = *(const float4*)(vbase + (size_t)(kb*64 + rr)*N3 + c4);
        }
        __syncthreads();
        float s[16];
        #pragma unroll
        for (int jj = 0; jj < 16; jj++) s[jj] = 0.f;
        #pragma unroll 8
        for (int d = 0; d < 64; d++) {
            float qv = Qs[r*FPITCH + d];
            #pragma unroll
            for (int jj = 0; jj < 16; jj++)
                s[jj] += qv * Ks[(jj*4 + cg)*FPITCH + d];
        }
        int qg = q0 + r;
        float smax = -1e30f;
        #pragma unroll
        for (int jj = 0; jj < 16; jj++) {
            int kg = kb*64 + jj*4 + cg;
            s[jj] = (kg <= qg) ? s[jj] * 0.03125f : -1e30f;
            smax = fmaxf(smax, s[jj]);
        }
        smax = fmaxf(smax, __shfl_xor_sync(0xffffffffu, smax, 1));
        smax = fmaxf(smax, __shfl_xor_sync(0xffffffffu, smax, 2));
        float mnew = fmaxf(mprev, smax);
        float corr = __expf(mprev - mnew);
        float psum = 0.f;
        #pragma unroll
        for (int jj = 0; jj < 16; jj++) {
            float p = __expf(s[jj] - mnew);
            Ps[r*FPITCH + jj*4 + cg] = p;
            psum += p;
        }
        psum += __shfl_xor_sync(0xffffffffu, psum, 1);
        psum += __shfl_xor_sync(0xffffffffu, psum, 2);
        l = l * corr + psum;
        mprev = mnew;
        #pragma unroll
        for (int i = 0; i < 16; i++) o[i] *= corr;
        __syncthreads();
        #pragma unroll 8
        for (int j = 0; j < 64; j++) {
            float p = Ps[r*FPITCH + j];
            #pragma unroll
            for (int dd = 0; dd < 16; dd++)
                o[dd] += p * Vs[j*FPITCH + dd*4 + cg];
        }
        __syncthreads();
    }
    float invl = 1.f / l;
    float* ob = att + (size_t)(b*Tk + q0 + r)*Ck + h*HSk;
    #pragma unroll
    for (int dd = 0; dd < 16; dd++)
        ob[dd*4 + cg] = o[dd] * invl;
}

// ---------------------------------------------------------------------------
extern "C" void kernel_launch(void* const* d_in, const int* in_sizes, int n_in,
                              void* d_out, int out_size) {
    const float* x     = (const float*)d_in[0];
    const float* ln1_g = (const float*)d_in[1];
    const float* ln1_b = (const float*)d_in[2];
    const float* ln2_g = (const float*)d_in[3];
    const float* ln2_b = (const float*)d_in[4];
    const float* Wq    = (const float*)d_in[5];
    const float* bq    = (const float*)d_in[6];
    const float* Wk    = (const float*)d_in[7];
    const float* bk    = (const float*)d_in[8];
    const float* Wv    = (const float*)d_in[9];
    const float* bv    = (const float*)d_in[10];
    const float* Wo    = (const float*)d_in[11];
    const float* bo    = (const float*)d_in[12];
    const float* W1    = (const float*)d_in[13];
    const float* b1    = (const float*)d_in[14];
    const float* W2    = (const float*)d_in[15];
    const float* b2    = (const float*)d_in[16];
    float* out = (float*)d_out;

    float *h1, *qkv, *att, *x2, *h2, *ffn, *wpack, *bpack;
    cudaGetSymbolAddress((void**)&h1,    g_h1);
    cudaGetSymbolAddress((void**)&qkv,   g_qkv);
    cudaGetSymbolAddress((void**)&att,   g_att);
    cudaGetSymbolAddress((void**)&x2,    g_x2);
    cudaGetSymbolAddress((void**)&h2,    g_h2);
    cudaGetSymbolAddress((void**)&ffn,   g_ffn);
    cudaGetSymbolAddress((void**)&wpack, g_wpack);
    cudaGetSymbolAddress((void**)&bpack, g_bpack);

    static int smem_set = 0;
    if (!smem_set) {
        cudaFuncSetAttribute(tgemm_kernel<false,false>, cudaFuncAttributeMaxDynamicSharedMemorySize, TG_SMEM);
        cudaFuncSetAttribute(tgemm_kernel<false,true>,  cudaFuncAttributeMaxDynamicSharedMemorySize, TG_SMEM);
        cudaFuncSetAttribute(tgemm_kernel<true,false>,  cudaFuncAttributeMaxDynamicSharedMemorySize, TG_SMEM);
        cudaFuncSetAttribute(flash_attn_kernel, cudaFuncAttributeMaxDynamicSharedMemorySize, 4*64*FPITCH*(int)sizeof(float));
        smem_set = 1;
    }

    // 1) pack qkv weights/biases
    pack_qkv_kernel<<<(Ck*Ck + 255)/256, 256>>>(Wq, Wk, Wv, bq, bk, bv);

    // 2) ln1(x) -> h1
    dim3 lnb(32, 8);
    ln_time_kernel<<<Bk*(Ck/32), lnb>>>(x, ln1_g, ln1_b, h1);

    // 3) qkv = h1 @ wpack + bpack   [8192 x 3072]
    tgemm_kernel<false,false><<<dim3(N3/128, MROWS/128), 256, TG_SMEM>>>(
        MROWS, N3, Ck, h1, wpack, bpack, nullptr, qkv);

    // 4) attention -> att [8192 x 1024]
    int fsm = 4*64*FPITCH*sizeof(float);
    flash_attn_kernel<<<Bk*Hk*(Tk/64), 256, fsm>>>(qkv, att);

    // 5) x2 = x + att @ Wo + bo
    tgemm_kernel<false,true><<<dim3(Ck/128, MROWS/128), 256, TG_SMEM>>>(
        MROWS, Ck, Ck, att, Wo, bo, x, x2);

    // 6) ln2(x2) -> h2
    ln_time_kernel<<<Bk*(Ck/32), lnb>>>(x2, ln2_g, ln2_b, h2);

    // 7) ffn = relu(h2 @ W1 + b1)  [8192 x 4096]
    tgemm_kernel<true,false><<<dim3(FF/128, MROWS/128), 256, TG_SMEM>>>(
        MROWS, FF, Ck, h2, W1, b1, nullptr, ffn);

    // 8) out = x2 + ffn @ W2 + b2
    tgemm_kernel<false,true><<<dim3(Ck/128, MROWS/128), 256, TG_SMEM>>>(
        MROWS, Ck, FF, ffn, W2, b2, x2, out);
}

// round 4
// speedup vs baseline: 3.2957x; 1.8084x over previous
#include <cuda_runtime.h>
#include <cuda_bf16.h>
#include <math.h>

#define Bk 4
#define Tk 2048
#define Ck 1024
#define Hk 16
#define HSk 64
#define EPSk 1e-5f
#define MROWS (Bk*Tk)          // 8192
#define N3 (3*Ck)              // 3072
#define FF (4*Ck)              // 4096

// ---------------- scratch (device globals: no allocation allowed) ----------
__device__ float g_h1[MROWS*Ck];
__device__ float g_qkv[MROWS*N3];
__device__ float g_att[MROWS*Ck];
__device__ float g_x2[MROWS*Ck];
__device__ float g_h2[MROWS*Ck];
__device__ float g_ffn[(size_t)MROWS*FF];
__device__ float g_wpack[Ck*N3];
__device__ float g_bpack[N3];

// ---------------- helpers ---------------------------------------------------
__device__ __forceinline__ void cp_async16(void* s, const void* g) {
    unsigned sa = (unsigned)__cvta_generic_to_shared(s);
    asm volatile("cp.async.cg.shared.global [%0], [%1], 16;\n" :: "r"(sa), "l"(g));
}
__device__ __forceinline__ void cp_commit() { asm volatile("cp.async.commit_group;\n"); }
__device__ __forceinline__ void cp_wait0()  { asm volatile("cp.async.wait_group 0;\n"); }

__device__ __forceinline__ unsigned f2tf(float f) {
    unsigned u;
    asm("cvt.rna.tf32.f32 %0, %1;" : "=r"(u) : "f"(f));
    return u;
}
__device__ __forceinline__ void mma1688(float* c, const unsigned* a, const unsigned* b) {
    asm volatile("mma.sync.aligned.m16n8k8.row.col.f32.tf32.tf32.f32 "
        "{%0,%1,%2,%3}, {%4,%5,%6,%7}, {%8,%9}, {%0,%1,%2,%3};"
        : "+f"(c[0]), "+f"(c[1]), "+f"(c[2]), "+f"(c[3])
        : "r"(a[0]), "r"(a[1]), "r"(a[2]), "r"(a[3]), "r"(b[0]), "r"(b[1]));
}

// ---------------- LayerNorm over TIME axis ---------------------------------
__global__ void ln_time_kernel(const float* __restrict__ x,
                               const float* __restrict__ g,
                               const float* __restrict__ beta,
                               float* __restrict__ out) {
    int cb = blockIdx.x % (Ck/32);
    int b  = blockIdx.x / (Ck/32);
    int tx = threadIdx.x, ty = threadIdx.y;
    int c  = cb*32 + tx;
    const float* xp = x + (size_t)b*Tk*Ck + c;
    float s = 0.f, s2 = 0.f;
    for (int t = ty; t < Tk; t += 8) {
        float v = xp[(size_t)t*Ck];
        s += v; s2 += v*v;
    }
    __shared__ float ss[8][32], ss2[8][32];
    ss[ty][tx] = s; ss2[ty][tx] = s2;
    __syncthreads();
    if (ty == 0) {
        for (int i = 1; i < 8; i++) { s += ss[i][tx]; s2 += ss2[i][tx]; }
        float m   = s / (float)Tk;
        float var = (s2 - (float)Tk*m*m) / (float)(Tk-1);
        float inv = rsqrtf(var + EPSk);
        ss[0][tx]  = m;
        ss2[0][tx] = inv;
    }
    __syncthreads();
    float m = ss[0][tx], inv = ss2[0][tx];
    float gg = g[c], bb = beta[c];
    float* op = out + (size_t)b*Tk*Ck + c;
    for (int t = ty; t < Tk; t += 8) {
        op[(size_t)t*Ck] = gg * (xp[(size_t)t*Ck] - m) * inv + bb;
    }
}

// ---------------- pack [H,C,HS] qkv weights into [C, 3C] -------------------
__global__ void pack_qkv_kernel(const float* __restrict__ Wq, const float* __restrict__ Wk,
                                const float* __restrict__ Wv, const float* __restrict__ bq,
                                const float* __restrict__ bk, const float* __restrict__ bv) {
    int i = blockIdx.x * blockDim.x + threadIdx.x;
    if (i < Ck*Ck) {
        int c = i / Ck;
        int n = i % Ck;
        int h = n / HSk, d = n % HSk;
        size_t src = (size_t)h*Ck*HSk + (size_t)c*HSk + d;
        g_wpack[(size_t)c*N3 + n]          = Wq[src];
        g_wpack[(size_t)c*N3 + Ck + n]     = Wk[src];
        g_wpack[(size_t)c*N3 + 2*Ck + n]   = Wv[src];
    }
    if (i < Ck) {
        g_bpack[i]        = bq[i];
        g_bpack[Ck + i]   = bk[i];
        g_bpack[2*Ck + i] = bv[i];
    }
}

// ---------------- tf32 tensor-core GEMM (unchanged from R2) ----------------
#define APITCH 36
#define BPITCH 136
#define TG_SMEM (2*128*APITCH*4 + 2*32*BPITCH*4)

template<bool RELU, bool RES>
__global__ void tgemm_kernel(int M, int N, int K,
                             const float* __restrict__ A,
                             const float* __restrict__ Bm,
                             const float* __restrict__ bias,
                             const float* __restrict__ res,
                             float* __restrict__ Cm) {
    extern __shared__ float smem[];
    float* As = smem;
    float* Bs = smem + 2*128*APITCH;
    int tid  = threadIdx.x;
    int lane = tid & 31, warp = tid >> 5;
    int warpM = warp & 1, warpN = warp >> 1;
    int bm0 = blockIdx.y * 128, bn0 = blockIdx.x * 128;

    float acc[4][4][4];
    #pragma unroll
    for (int a = 0; a < 4; a++)
        #pragma unroll
        for (int b = 0; b < 4; b++)
            #pragma unroll
            for (int c = 0; c < 4; c++) acc[a][b][c] = 0.f;

    auto load_tiles = [&](int k0, int buf) {
        float* ad = As + buf*128*APITCH;
        #pragma unroll
        for (int i = 0; i < 4; i++) {
            int id = tid + i*256;
            int row = id >> 3, cc = (id & 7) << 2;
            cp_async16(ad + row*APITCH + cc, A + (size_t)(bm0+row)*K + k0 + cc);
        }
        float* bd = Bs + buf*32*BPITCH;
        #pragma unroll
        for (int i = 0; i < 4; i++) {
            int id = tid + i*256;
            int row = id >> 5, cc = (id & 31) << 2;
            cp_async16(bd + row*BPITCH + cc, Bm + (size_t)(k0+row)*N + bn0 + cc);
        }
    };

    load_tiles(0, 0);
    cp_commit();
    int nk = K / 32;
    for (int t = 0; t < nk; t++) {
        cp_wait0();
        __syncthreads();
        if (t + 1 < nk) { load_tiles((t+1)*32, (t+1) & 1); cp_commit(); }
        const float* Ab = As + (t & 1)*128*APITCH;
        const float* Bb = Bs + (t & 1)*32*BPITCH;
        #pragma unroll
        for (int kk = 0; kk < 4; kk++) {
            int kc = kk * 8;
            unsigned af[4][4], bf[4][2];
            #pragma unroll
            for (int mt = 0; mt < 4; mt++) {
                int r0 = warpM*64 + mt*16 + (lane >> 2);
                int c0 = kc + (lane & 3);
                af[mt][0] = f2tf(Ab[r0*APITCH + c0]);
                af[mt][1] = f2tf(Ab[(r0+8)*APITCH + c0]);
                af[mt][2] = f2tf(Ab[r0*APITCH + c0 + 4]);
                af[mt][3] = f2tf(Ab[(r0+8)*APITCH + c0 + 4]);
            }
            #pragma unroll
            for (int nt = 0; nt < 4; nt++) {
                int kr = kc + (lane & 3);
                int nc = warpN*32 + nt*8 + (lane >> 2);
                bf[nt][0] = f2tf(Bb[kr*BPITCH + nc]);
                bf[nt][1] = f2tf(Bb[(kr+4)*BPITCH + nc]);
            }
            #pragma unroll
            for (int mt = 0; mt < 4; mt++)
                #pragma unroll
                for (int nt = 0; nt < 4; nt++)
                    mma1688(acc[mt][nt], af[mt], bf[nt]);
        }
        __syncthreads();
    }

    #pragma unroll
    for (int mt = 0; mt < 4; mt++) {
        #pragma unroll
        for (int nt = 0; nt < 4; nt++) {
            #pragma unroll
            for (int half = 0; half < 2; half++) {
                int row = bm0 + warpM*64 + mt*16 + (lane >> 2) + half*8;
                int col = bn0 + warpN*32 + nt*8 + 2*(lane & 3);
                float v0 = acc[mt][nt][half*2+0] + bias[col];
                float v1 = acc[mt][nt][half*2+1] + bias[col+1];
                if (RES) {
                    v0 += res[(size_t)row*N + col];
                    v1 += res[(size_t)row*N + col + 1];
                }
                if (RELU) { v0 = fmaxf(v0, 0.f); v1 = fmaxf(v1, 0.f); }
                *(float2*)&Cm[(size_t)row*N + col] = make_float2(v0, v1);
            }
        }
    }
}

// ---------------- tensor-core flash attention (tf32, causal) ---------------
// block = 128 threads (4 warps), each warp owns 16 of the 64 query rows.
// Qs/Ks/Ps pitch 68 (A & B frag loads conflict-free: 4g+c), Vs pitch 72 (8c+g).
#define PQ 68
#define PV 72
#define FA_SMEM ((64*PQ + 64*PQ + 64*PV + 64*PQ) * 4)

__global__ void flash_tc_kernel(const float* __restrict__ qkv, float* __restrict__ att) {
    extern __shared__ float sm[];
    float* Qs = sm;                 // [64][PQ]
    float* Ks = Qs + 64*PQ;         // [64][PQ]  (key-major [key][d])
    float* Vs = Ks + 64*PQ;         // [64][PV]  (key-major [key][d])
    float* Ps = Vs + 64*PV;         // [64][PQ]

    int tid  = threadIdx.x;
    int lane = tid & 31, warp = tid >> 5;
    int g = lane >> 2, c = lane & 3;

    const int ntiles = Tk / 64;
    int qt = blockIdx.x % ntiles;
    int h  = (blockIdx.x / ntiles) % Hk;
    int b  =  blockIdx.x / (ntiles * Hk);
    int q0 = qt * 64;
    const float* qbase = qkv + (size_t)b*Tk*N3 + h*HSk;
    const float* kbase = qbase + Ck;
    const float* vbase = qbase + 2*Ck;

    // stage Q
    for (int i = tid; i < 64*16; i += 128) {
        int r = i >> 4, c4 = (i & 15) << 2;
        *(float4*)&Qs[r*PQ + c4] = *(const float4*)(qbase + (size_t)(q0 + r)*N3 + c4);
    }
    __syncthreads();

    // hoist Q fragments (tf32) — row block = warp*16
    int rl = warp*16 + g;           // local A row
    unsigned qa[8][4];
    #pragma unroll
    for (int kc = 0; kc < 8; kc++) {
        int k0 = kc*8 + c;
        qa[kc][0] = f2tf(Qs[rl*PQ + k0]);
        qa[kc][1] = f2tf(Qs[(rl+8)*PQ + k0]);
        qa[kc][2] = f2tf(Qs[rl*PQ + k0 + 4]);
        qa[kc][3] = f2tf(Qs[(rl+8)*PQ + k0 + 4]);
    }

    float m0 = -1e30f, m1 = -1e30f, l0 = 0.f, l1 = 0.f;
    float o[8][4];
    #pragma unroll
    for (int nt = 0; nt < 8; nt++)
        #pragma unroll
        for (int i = 0; i < 4; i++) o[nt][i] = 0.f;

    int row0 = q0 + rl;             // global query rows for this thread
    int row1 = row0 + 8;
    int nkb = q0/64 + 1;

    for (int kb = 0; kb < nkb; kb++) {
        __syncthreads();            // previous iter's reads of Ks/Vs done
        for (int i = tid; i < 64*16; i += 128) {
            int rr = i >> 4, c4 = (i & 15) << 2;
            *(float4*)&Ks[rr*PQ + c4] = *(const float4*)(kbase + (size_t)(kb*64 + rr)*N3 + c4);
            *(float4*)&Vs[rr*PV + c4] = *(const float4*)(vbase + (size_t)(kb*64 + rr)*N3 + c4);
        }
        __syncthreads();

        // S = Q @ K^T : B element (k=d, n=key) = Ks[key][d]
        float s[8][4];
        #pragma unroll
        for (int nt = 0; nt < 8; nt++)
            #pragma unroll
            for (int i = 0; i < 4; i++) s[nt][i] = 0.f;
        #pragma unroll
        for (int kc = 0; kc < 8; kc++) {
            int kr = kc*8 + c;
            #pragma unroll
            for (int nt = 0; nt < 8; nt++) {
                unsigned bf[2];
                int nc = nt*8 + g;
                bf[0] = f2tf(Ks[nc*PQ + kr]);
                bf[1] = f2tf(Ks[nc*PQ + kr + 4]);
                mma1688(s[nt], qa[kc], bf);
            }
        }

        // mask + scale + online softmax
        float rmax0 = -1e30f, rmax1 = -1e30f;
        #pragma unroll
        for (int nt = 0; nt < 8; nt++) {
            int col = kb*64 + nt*8 + 2*c;
            s[nt][0] = (col   <= row0) ? s[nt][0]*0.03125f : -1e30f;
            s[nt][1] = (col+1 <= row0) ? s[nt][1]*0.03125f : -1e30f;
            s[nt][2] = (col   <= row1) ? s[nt][2]*0.03125f : -1e30f;
            s[nt][3] = (col+1 <= row1) ? s[nt][3]*0.03125f : -1e30f;
            rmax0 = fmaxf(rmax0, fmaxf(s[nt][0], s[nt][1]));
            rmax1 = fmaxf(rmax1, fmaxf(s[nt][2], s[nt][3]));
        }
        rmax0 = fmaxf(rmax0, __shfl_xor_sync(0xffffffffu, rmax0, 1));
        rmax0 = fmaxf(rmax0, __shfl_xor_sync(0xffffffffu, rmax0, 2));
        rmax1 = fmaxf(rmax1, __shfl_xor_sync(0xffffffffu, rmax1, 1));
        rmax1 = fmaxf(rmax1, __shfl_xor_sync(0xffffffffu, rmax1, 2));
        float mn0 = fmaxf(m0, rmax0), mn1 = fmaxf(m1, rmax1);
        float corr0 = __expf(m0 - mn0), corr1 = __expf(m1 - mn1);
        float ps0 = 0.f, ps1 = 0.f;
        #pragma unroll
        for (int nt = 0; nt < 8; nt++) {
            float p0 = __expf(s[nt][0] - mn0);
            float p1 = __expf(s[nt][1] - mn0);
            float p2 = __expf(s[nt][2] - mn1);
            float p3 = __expf(s[nt][3] - mn1);
            ps0 += p0 + p1; ps1 += p2 + p3;
            int cl = nt*8 + 2*c;
            *(float2*)&Ps[rl*PQ + cl]     = make_float2(p0, p1);
            *(float2*)&Ps[(rl+8)*PQ + cl] = make_float2(p2, p3);
        }
        ps0 += __shfl_xor_sync(0xffffffffu, ps0, 1);
        ps0 += __shfl_xor_sync(0xffffffffu, ps0, 2);
        ps1 += __shfl_xor_sync(0xffffffffu, ps1, 1);
        ps1 += __shfl_xor_sync(0xffffffffu, ps1, 2);
        l0 = l0*corr0 + ps0;  l1 = l1*corr1 + ps1;
        m0 = mn0; m1 = mn1;
        #pragma unroll
        for (int nt = 0; nt < 8; nt++) {
            o[nt][0] *= corr0; o[nt][1] *= corr0;
            o[nt][2] *= corr1; o[nt][3] *= corr1;
        }
        __syncwarp();   // Ps rows of this warp written by this warp only

        // O += P @ V : A = Ps (own rows), B element (k=key, n=d) = Vs[key][d]
        #pragma unroll
        for (int kc = 0; kc < 8; kc++) {
            int k0 = kc*8 + c;
            unsigned pa[4];
            pa[0] = f2tf(Ps[rl*PQ + k0]);
            pa[1] = f2tf(Ps[(rl+8)*PQ + k0]);
            pa[2] = f2tf(Ps[rl*PQ + k0 + 4]);
            pa[3] = f2tf(Ps[(rl+8)*PQ + k0 + 4]);
            #pragma unroll
            for (int nt = 0; nt < 8; nt++) {
                unsigned bf[2];
                int nc = nt*8 + g;
                bf[0] = f2tf(Vs[k0*PV + nc]);
                bf[1] = f2tf(Vs[(k0+4)*PV + nc]);
                mma1688(o[nt], pa, bf);
            }
        }
    }

    float inv0 = 1.f / l0, inv1 = 1.f / l1;
    float* ob0 = att + (size_t)(b*Tk + row0)*Ck + h*HSk;
    float* ob1 = att + (size_t)(b*Tk + row1)*Ck + h*HSk;
    #pragma unroll
    for (int nt = 0; nt < 8; nt++) {
        int cl = nt*8 + 2*c;
        *(float2*)&ob0[cl] = make_float2(o[nt][0]*inv0, o[nt][1]*inv0);
        *(float2*)&ob1[cl] = make_float2(o[nt][2]*inv1, o[nt][3]*inv1);
    }
}

// ---------------------------------------------------------------------------
extern "C" void kernel_launch(void* const* d_in, const int* in_sizes, int n_in,
                              void* d_out, int out_size) {
    const float* x     = (const float*)d_in[0];
    const float* ln1_g = (const float*)d_in[1];
    const float* ln1_b = (const float*)d_in[2];
    const float* ln2_g = (const float*)d_in[3];
    const float* ln2_b = (const float*)d_in[4];
    const float* Wq    = (const float*)d_in[5];
    const float* bq    = (const float*)d_in[6];
    const float* Wk    = (const float*)d_in[7];
    const float* bk    = (const float*)d_in[8];
    const float* Wv    = (const float*)d_in[9];
    const float* bv    = (const float*)d_in[10];
    const float* Wo    = (const float*)d_in[11];
    const float* bo    = (const float*)d_in[12];
    const float* W1    = (const float*)d_in[13];
    const float* b1    = (const float*)d_in[14];
    const float* W2    = (const float*)d_in[15];
    const float* b2    = (const float*)d_in[16];
    float* out = (float*)d_out;

    float *h1, *qkv, *att, *x2, *h2, *ffn, *wpack, *bpack;
    cudaGetSymbolAddress((void**)&h1,    g_h1);
    cudaGetSymbolAddress((void**)&qkv,   g_qkv);
    cudaGetSymbolAddress((void**)&att,   g_att);
    cudaGetSymbolAddress((void**)&x2,    g_x2);
    cudaGetSymbolAddress((void**)&h2,    g_h2);
    cudaGetSymbolAddress((void**)&ffn,   g_ffn);
    cudaGetSymbolAddress((void**)&wpack, g_wpack);
    cudaGetSymbolAddress((void**)&bpack, g_bpack);

    cudaFuncSetAttribute(tgemm_kernel<false,false>, cudaFuncAttributeMaxDynamicSharedMemorySize, TG_SMEM);
    cudaFuncSetAttribute(tgemm_kernel<false,true>,  cudaFuncAttributeMaxDynamicSharedMemorySize, TG_SMEM);
    cudaFuncSetAttribute(tgemm_kernel<true,false>,  cudaFuncAttributeMaxDynamicSharedMemorySize, TG_SMEM);
    cudaFuncSetAttribute(flash_tc_kernel, cudaFuncAttributeMaxDynamicSharedMemorySize, FA_SMEM);

    // 1) pack qkv weights/biases
    pack_qkv_kernel<<<(Ck*Ck + 255)/256, 256>>>(Wq, Wk, Wv, bq, bk, bv);

    // 2) ln1(x) -> h1
    dim3 lnb(32, 8);
    ln_time_kernel<<<Bk*(Ck/32), lnb>>>(x, ln1_g, ln1_b, h1);

    // 3) qkv = h1 @ wpack + bpack   [8192 x 3072]
    tgemm_kernel<false,false><<<dim3(N3/128, MROWS/128), 256, TG_SMEM>>>(
        MROWS, N3, Ck, h1, wpack, bpack, nullptr, qkv);

    // 4) attention -> att [8192 x 1024]
    flash_tc_kernel<<<Bk*Hk*(Tk/64), 128, FA_SMEM>>>(qkv, att);

    // 5) x2 = x + att @ Wo + bo
    tgemm_kernel<false,true><<<dim3(Ck/128, MROWS/128), 256, TG_SMEM>>>(
        MROWS, Ck, Ck, att, Wo, bo, x, x2);

    // 6) ln2(x2) -> h2
    ln_time_kernel<<<Bk*(Ck/32), lnb>>>(x2, ln2_g, ln2_b, h2);

    // 7) ffn = relu(h2 @ W1 + b1)  [8192 x 4096]
    tgemm_kernel<true,false><<<dim3(FF/128, MROWS/128), 256, TG_SMEM>>>(
        MROWS, FF, Ck, h2, W1, b1, nullptr, ffn);

    // 8) out = x2 + ffn @ W2 + b2
    tgemm_kernel<false,true><<<dim3(Ck/128, MROWS/128), 256, TG_SMEM>>>(
        MROWS, Ck, FF, ffn, W2, b2, x2, out);
}

// round 5
// speedup vs baseline: 4.0302x; 1.2229x over previous
#include <cuda_runtime.h>
#include <cuda_bf16.h>
#include <math.h>

#define Bk 4
#define Tk 2048
#define Ck 1024
#define Hk 16
#define HSk 64
#define EPSk 1e-5f
#define MROWS (Bk*Tk)          // 8192
#define N3 (3*Ck)              // 3072
#define FF (4*Ck)              // 4096

// ---------------- scratch (device globals: no allocation allowed) ----------
__device__ float g_h1[MROWS*Ck];          // tf32 bits
__device__ float g_qkv[MROWS*N3];         // tf32 bits
__device__ float g_att[MROWS*Ck];         // tf32 bits
__device__ float g_x2[MROWS*Ck];          // fp32
__device__ float g_h2[MROWS*Ck];          // tf32 bits
__device__ float g_ffn[(size_t)MROWS*FF]; // tf32 bits
__device__ float g_wpack[Ck*N3];          // tf32 bits
__device__ float g_bpack[N3];             // fp32
__device__ float g_wo32[Ck*Ck];           // tf32 bits
__device__ float g_w132[(size_t)Ck*FF];   // tf32 bits
__device__ float g_w232[(size_t)FF*Ck];   // tf32 bits

// ---------------- helpers ---------------------------------------------------
__device__ __forceinline__ void cp_async16(void* s, const void* g) {
    unsigned sa = (unsigned)__cvta_generic_to_shared(s);
    asm volatile("cp.async.cg.shared.global [%0], [%1], 16;\n" :: "r"(sa), "l"(g));
}
__device__ __forceinline__ void cp_commit() { asm volatile("cp.async.commit_group;\n"); }
__device__ __forceinline__ void cp_wait1()  { asm volatile("cp.async.wait_group 1;\n"); }

__device__ __forceinline__ unsigned f2tf(float f) {
    unsigned u;
    asm("cvt.rna.tf32.f32 %0, %1;" : "=r"(u) : "f"(f));
    return u;
}
__device__ __forceinline__ float tfbits(float f) { return __uint_as_float(f2tf(f)); }

__device__ __forceinline__ void mma1688(float* c, const unsigned* a, const unsigned* b) {
    asm volatile("mma.sync.aligned.m16n8k8.row.col.f32.tf32.tf32.f32 "
        "{%0,%1,%2,%3}, {%4,%5,%6,%7}, {%8,%9}, {%0,%1,%2,%3};"
        : "+f"(c[0]), "+f"(c[1]), "+f"(c[2]), "+f"(c[3])
        : "r"(a[0]), "r"(a[1]), "r"(a[2]), "r"(a[3]), "r"(b[0]), "r"(b[1]));
}

// ---------------- generic fp32 -> tf32-bits convert ------------------------
__global__ void cvt_tf32_kernel(const float* __restrict__ src, float* __restrict__ dst, int n4) {
    int i = blockIdx.x * blockDim.x + threadIdx.x;
    if (i < n4) {
        float4 v = ((const float4*)src)[i];
        v.x = tfbits(v.x); v.y = tfbits(v.y); v.z = tfbits(v.z); v.w = tfbits(v.w);
        ((float4*)dst)[i] = v;
    }
}

// ---------------- LayerNorm over TIME axis (emits tf32 bits) ---------------
__global__ void ln_time_kernel(const float* __restrict__ x,
                               const float* __restrict__ g,
                               const float* __restrict__ beta,
                               float* __restrict__ out) {
    int cb = blockIdx.x % (Ck/32);
    int b  = blockIdx.x / (Ck/32);
    int tx = threadIdx.x, ty = threadIdx.y;
    int c  = cb*32 + tx;
    const float* xp = x + (size_t)b*Tk*Ck + c;
    float s = 0.f, s2 = 0.f;
    for (int t = ty; t < Tk; t += 8) {
        float v = xp[(size_t)t*Ck];
        s += v; s2 += v*v;
    }
    __shared__ float ss[8][32], ss2[8][32];
    ss[ty][tx] = s; ss2[ty][tx] = s2;
    __syncthreads();
    if (ty == 0) {
        for (int i = 1; i < 8; i++) { s += ss[i][tx]; s2 += ss2[i][tx]; }
        float m   = s / (float)Tk;
        float var = (s2 - (float)Tk*m*m) / (float)(Tk-1);
        float inv = rsqrtf(var + EPSk);
        ss[0][tx]  = m;
        ss2[0][tx] = inv;
    }
    __syncthreads();
    float m = ss[0][tx], inv = ss2[0][tx];
    float gg = g[c], bb = beta[c];
    float* op = out + (size_t)b*Tk*Ck + c;
    for (int t = ty; t < Tk; t += 8) {
        op[(size_t)t*Ck] = tfbits(gg * (xp[(size_t)t*Ck] - m) * inv + bb);
    }
}

// ---------------- pack [H,C,HS] qkv weights into [C, 3C] tf32 bits ---------
__global__ void pack_qkv_kernel(const float* __restrict__ Wq, const float* __restrict__ Wk,
                                const float* __restrict__ Wv, const float* __restrict__ bq,
                                const float* __restrict__ bk, const float* __restrict__ bv) {
    int i = blockIdx.x * blockDim.x + threadIdx.x;
    if (i < Ck*Ck) {
        int c = i / Ck;
        int n = i % Ck;
        int h = n / HSk, d = n % HSk;
        size_t src = (size_t)h*Ck*HSk + (size_t)c*HSk + d;
        g_wpack[(size_t)c*N3 + n]          = tfbits(Wq[src]);
        g_wpack[(size_t)c*N3 + Ck + n]     = tfbits(Wk[src]);
        g_wpack[(size_t)c*N3 + 2*Ck + n]   = tfbits(Wv[src]);
    }
    if (i < Ck) {
        g_bpack[i]        = bq[i];
        g_bpack[Ck + i]   = bk[i];
        g_bpack[2*Ck + i] = bv[i];
    }
}

// ---------------- tf32 tensor-core GEMM (operands pre-rounded) -------------
#define APITCH 36
#define BPITCH 136
#define STG (128*APITCH + 32*BPITCH)
#define TG_SMEM (3*STG*4)

template<bool RELU, bool RES, bool OTF>
__global__ __launch_bounds__(256, 2)
void tgemm_kernel(int M, int N, int K,
                  const float* __restrict__ A,
                  const float* __restrict__ Bm,
                  const float* __restrict__ bias,
                  const float* __restrict__ res,
                  float* __restrict__ Cm) {
    extern __shared__ float smem[];
    int tid  = threadIdx.x;
    int lane = tid & 31, warp = tid >> 5;
    int warpM = warp & 1, warpN = warp >> 1;
    int bm0 = blockIdx.y * 128, bn0 = blockIdx.x * 128;

    float acc[4][4][4];
    #pragma unroll
    for (int a = 0; a < 4; a++)
        #pragma unroll
        for (int b = 0; b < 4; b++)
            #pragma unroll
            for (int c = 0; c < 4; c++) acc[a][b][c] = 0.f;

    auto load_tiles = [&](int k0, int buf) {
        float* ad = smem + buf*STG;
        #pragma unroll
        for (int i = 0; i < 4; i++) {
            int id = tid + i*256;
            int row = id >> 3, cc = (id & 7) << 2;
            cp_async16(ad + row*APITCH + cc, A + (size_t)(bm0+row)*K + k0 + cc);
        }
        float* bd = smem + buf*STG + 128*APITCH;
        #pragma unroll
        for (int i = 0; i < 4; i++) {
            int id = tid + i*256;
            int row = id >> 5, cc = (id & 31) << 2;
            cp_async16(bd + row*BPITCH + cc, Bm + (size_t)(k0+row)*N + bn0 + cc);
        }
    };

    int nk = K / 32;
    load_tiles(0, 0); cp_commit();
    load_tiles(32, 1); cp_commit();
    for (int t = 0; t < nk; t++) {
        cp_wait1();
        __syncthreads();
        if (t + 2 < nk) load_tiles((t+2)*32, (t+2) % 3);
        cp_commit();
        const unsigned* Ab = (const unsigned*)(smem + (t%3)*STG);
        const unsigned* Bb = (const unsigned*)(smem + (t%3)*STG + 128*APITCH);
        #pragma unroll
        for (int kk = 0; kk < 4; kk++) {
            int kc = kk * 8;
            unsigned af[4][4], bf[4][2];
            #pragma unroll
            for (int mt = 0; mt < 4; mt++) {
                int r0 = warpM*64 + mt*16 + (lane >> 2);
                int c0 = kc + (lane & 3);
                af[mt][0] = Ab[r0*APITCH + c0];
                af[mt][1] = Ab[(r0+8)*APITCH + c0];
                af[mt][2] = Ab[r0*APITCH + c0 + 4];
                af[mt][3] = Ab[(r0+8)*APITCH + c0 + 4];
            }
            #pragma unroll
            for (int nt = 0; nt < 4; nt++) {
                int kr = kc + (lane & 3);
                int nc = warpN*32 + nt*8 + (lane >> 2);
                bf[nt][0] = Bb[kr*BPITCH + nc];
                bf[nt][1] = Bb[(kr+4)*BPITCH + nc];
            }
            #pragma unroll
            for (int mt = 0; mt < 4; mt++)
                #pragma unroll
                for (int nt = 0; nt < 4; nt++)
                    mma1688(acc[mt][nt], af[mt], bf[nt]);
        }
        __syncthreads();
    }

    #pragma unroll
    for (int mt = 0; mt < 4; mt++) {
        #pragma unroll
        for (int nt = 0; nt < 4; nt++) {
            #pragma unroll
            for (int half = 0; half < 2; half++) {
                int row = bm0 + warpM*64 + mt*16 + (lane >> 2) + half*8;
                int col = bn0 + warpN*32 + nt*8 + 2*(lane & 3);
                float v0 = acc[mt][nt][half*2+0] + bias[col];
                float v1 = acc[mt][nt][half*2+1] + bias[col+1];
                if (RES) {
                    v0 += res[(size_t)row*N + col];
                    v1 += res[(size_t)row*N + col + 1];
                }
                if (RELU) { v0 = fmaxf(v0, 0.f); v1 = fmaxf(v1, 0.f); }
                if (OTF)  { v0 = tfbits(v0); v1 = tfbits(v1); }
                *(float2*)&Cm[(size_t)row*N + col] = make_float2(v0, v1);
            }
        }
    }
}

// ---------------- tensor-core flash attention (tf32-bit inputs) ------------
#define PQ 68
#define PV 72
#define FA_SMEM ((64*PQ + 64*PQ + 64*PV) * 4)   // Ps aliases Qs

__global__ __launch_bounds__(128, 4)
void flash_tc_kernel(const float* __restrict__ qkv, float* __restrict__ att) {
    extern __shared__ float sm[];
    float* Qs = sm;                 // [64][PQ]; reused as Ps after hoist
    float* Ks = Qs + 64*PQ;         // [64][PQ]
    float* Vs = Ks + 64*PQ;         // [64][PV]
    float* Ps = Qs;

    int tid  = threadIdx.x;
    int lane = tid & 31, warp = tid >> 5;
    int g = lane >> 2, c = lane & 3;

    const int ntiles = Tk / 64;
    int qt = (ntiles - 1) - (blockIdx.x % ntiles);   // longest first
    int h  = (blockIdx.x / ntiles) % Hk;
    int b  =  blockIdx.x / (ntiles * Hk);
    int q0 = qt * 64;
    const float* qbase = qkv + (size_t)b*Tk*N3 + h*HSk;
    const float* kbase = qbase + Ck;
    const float* vbase = qbase + 2*Ck;

    for (int i = tid; i < 64*16; i += 128) {
        int r = i >> 4, c4 = (i & 15) << 2;
        *(float4*)&Qs[r*PQ + c4] = *(const float4*)(qbase + (size_t)(q0 + r)*N3 + c4);
    }
    __syncthreads();

    int rl = warp*16 + g;
    unsigned qa[8][4];
    const unsigned* Qu = (const unsigned*)Qs;
    #pragma unroll
    for (int kc = 0; kc < 8; kc++) {
        int k0 = kc*8 + c;
        qa[kc][0] = Qu[rl*PQ + k0];
        qa[kc][1] = Qu[(rl+8)*PQ + k0];
        qa[kc][2] = Qu[rl*PQ + k0 + 4];
        qa[kc][3] = Qu[(rl+8)*PQ + k0 + 4];
    }

    float m0 = -1e30f, m1 = -1e30f, l0 = 0.f, l1 = 0.f;
    float o[8][4];
    #pragma unroll
    for (int nt = 0; nt < 8; nt++)
        #pragma unroll
        for (int i = 0; i < 4; i++) o[nt][i] = 0.f;

    int row0 = q0 + rl;
    int row1 = row0 + 8;
    int nkb = q0/64 + 1;
    const unsigned* Ku = (const unsigned*)Ks;
    const unsigned* Vu = (const unsigned*)Vs;
    const unsigned* Pu = (const unsigned*)Ps;

    for (int kb = 0; kb < nkb; kb++) {
        __syncthreads();
        for (int i = tid; i < 64*16; i += 128) {
            int rr = i >> 4, c4 = (i & 15) << 2;
            *(float4*)&Ks[rr*PQ + c4] = *(const float4*)(kbase + (size_t)(kb*64 + rr)*N3 + c4);
            *(float4*)&Vs[rr*PV + c4] = *(const float4*)(vbase + (size_t)(kb*64 + rr)*N3 + c4);
        }
        __syncthreads();

        float s[8][4];
        #pragma unroll
        for (int nt = 0; nt < 8; nt++)
            #pragma unroll
            for (int i = 0; i < 4; i++) s[nt][i] = 0.f;
        #pragma unroll
        for (int kc = 0; kc < 8; kc++) {
            int kr = kc*8 + c;
            #pragma unroll
            for (int nt = 0; nt < 8; nt++) {
                unsigned bf[2];
                int nc = nt*8 + g;
                bf[0] = Ku[nc*PQ + kr];
                bf[1] = Ku[nc*PQ + kr + 4];
                mma1688(s[nt], qa[kc], bf);
            }
        }

        float rmax0 = -1e30f, rmax1 = -1e30f;
        #pragma unroll
        for (int nt = 0; nt < 8; nt++) {
            int col = kb*64 + nt*8 + 2*c;
            s[nt][0] = (col   <= row0) ? s[nt][0]*0.03125f : -1e30f;
            s[nt][1] = (col+1 <= row0) ? s[nt][1]*0.03125f : -1e30f;
            s[nt][2] = (col   <= row1) ? s[nt][2]*0.03125f : -1e30f;
            s[nt][3] = (col+1 <= row1) ? s[nt][3]*0.03125f : -1e30f;
            rmax0 = fmaxf(rmax0, fmaxf(s[nt][0], s[nt][1]));
            rmax1 = fmaxf(rmax1, fmaxf(s[nt][2], s[nt][3]));
        }
        rmax0 = fmaxf(rmax0, __shfl_xor_sync(0xffffffffu, rmax0, 1));
        rmax0 = fmaxf(rmax0, __shfl_xor_sync(0xffffffffu, rmax0, 2));
        rmax1 = fmaxf(rmax1, __shfl_xor_sync(0xffffffffu, rmax1, 1));
        rmax1 = fmaxf(rmax1, __shfl_xor_sync(0xffffffffu, rmax1, 2));
        float mn0 = fmaxf(m0, rmax0), mn1 = fmaxf(m1, rmax1);
        float corr0 = __expf(m0 - mn0), corr1 = __expf(m1 - mn1);
        float ps0 = 0.f, ps1 = 0.f;
        #pragma unroll
        for (int nt = 0; nt < 8; nt++) {
            float p0 = __expf(s[nt][0] - mn0);
            float p1 = __expf(s[nt][1] - mn0);
            float p2 = __expf(s[nt][2] - mn1);
            float p3 = __expf(s[nt][3] - mn1);
            ps0 += p0 + p1; ps1 += p2 + p3;
            int cl = nt*8 + 2*c;
            *(float2*)&Ps[rl*PQ + cl]     = make_float2(__uint_as_float(f2tf(p0)), __uint_as_float(f2tf(p1)));
            *(float2*)&Ps[(rl+8)*PQ + cl] = make_float2(__uint_as_float(f2tf(p2)), __uint_as_float(f2tf(p3)));
        }
        ps0 += __shfl_xor_sync(0xffffffffu, ps0, 1);
        ps0 += __shfl_xor_sync(0xffffffffu, ps0, 2);
        ps1 += __shfl_xor_sync(0xffffffffu, ps1, 1);
        ps1 += __shfl_xor_sync(0xffffffffu, ps1, 2);
        l0 = l0*corr0 + ps0;  l1 = l1*corr1 + ps1;
        m0 = mn0; m1 = mn1;
        #pragma unroll
        for (int nt = 0; nt < 8; nt++) {
            o[nt][0] *= corr0; o[nt][1] *= corr0;
            o[nt][2] *= corr1; o[nt][3] *= corr1;
        }
        __syncwarp();

        #pragma unroll
        for (int kc = 0; kc < 8; kc++) {
            int k0 = kc*8 + c;
            unsigned pa[4];
            pa[0] = Pu[rl*PQ + k0];
            pa[1] = Pu[(rl+8)*PQ + k0];
            pa[2] = Pu[rl*PQ + k0 + 4];
            pa[3] = Pu[(rl+8)*PQ + k0 + 4];
            #pragma unroll
            for (int nt = 0; nt < 8; nt++) {
                unsigned bf[2];
                int nc = nt*8 + g;
                bf[0] = Vu[k0*PV + nc];
                bf[1] = Vu[(k0+4)*PV + nc];
                mma1688(o[nt], pa, bf);
            }
        }
    }

    float inv0 = 1.f / l0, inv1 = 1.f / l1;
    float* ob0 = att + (size_t)(b*Tk + row0)*Ck + h*HSk;
    float* ob1 = att + (size_t)(b*Tk + row1)*Ck + h*HSk;
    #pragma unroll
    for (int nt = 0; nt < 8; nt++) {
        int cl = nt*8 + 2*c;
        *(float2*)&ob0[cl] = make_float2(tfbits(o[nt][0]*inv0), tfbits(o[nt][1]*inv0));
        *(float2*)&ob1[cl] = make_float2(tfbits(o[nt][2]*inv1), tfbits(o[nt][3]*inv1));
    }
}

// ---------------------------------------------------------------------------
extern "C" void kernel_launch(void* const* d_in, const int* in_sizes, int n_in,
                              void* d_out, int out_size) {
    const float* x     = (const float*)d_in[0];
    const float* ln1_g = (const float*)d_in[1];
    const float* ln1_b = (const float*)d_in[2];
    const float* ln2_g = (const float*)d_in[3];
    const float* ln2_b = (const float*)d_in[4];
    const float* Wq    = (const float*)d_in[5];
    const float* bq    = (const float*)d_in[6];
    const float* Wk    = (const float*)d_in[7];
    const float* bk    = (const float*)d_in[8];
    const float* Wv    = (const float*)d_in[9];
    const float* bv    = (const float*)d_in[10];
    const float* Wo    = (const float*)d_in[11];
    const float* bo    = (const float*)d_in[12];
    const float* W1    = (const float*)d_in[13];
    const float* b1    = (const float*)d_in[14];
    const float* W2    = (const float*)d_in[15];
    const float* b2    = (const float*)d_in[16];
    float* out = (float*)d_out;

    float *h1, *qkv, *att, *x2, *h2, *ffn, *wpack, *bpack, *wo32, *w132, *w232;
    cudaGetSymbolAddress((void**)&h1,    g_h1);
    cudaGetSymbolAddress((void**)&qkv,   g_qkv);
    cudaGetSymbolAddress((void**)&att,   g_att);
    cudaGetSymbolAddress((void**)&x2,    g_x2);
    cudaGetSymbolAddress((void**)&h2,    g_h2);
    cudaGetSymbolAddress((void**)&ffn,   g_ffn);
    cudaGetSymbolAddress((void**)&wpack, g_wpack);
    cudaGetSymbolAddress((void**)&bpack, g_bpack);
    cudaGetSymbolAddress((void**)&wo32,  g_wo32);
    cudaGetSymbolAddress((void**)&w132,  g_w132);
    cudaGetSymbolAddress((void**)&w232,  g_w232);

    cudaFuncSetAttribute(tgemm_kernel<false,false,true>, cudaFuncAttributeMaxDynamicSharedMemorySize, TG_SMEM);
    cudaFuncSetAttribute(tgemm_kernel<false,true,false>, cudaFuncAttributeMaxDynamicSharedMemorySize, TG_SMEM);
    cudaFuncSetAttribute(tgemm_kernel<true,false,true>,  cudaFuncAttributeMaxDynamicSharedMemorySize, TG_SMEM);
    cudaFuncSetAttribute(flash_tc_kernel, cudaFuncAttributeMaxDynamicSharedMemorySize, FA_SMEM);

    // 0) convert weights to tf32 bits
    pack_qkv_kernel<<<(Ck*Ck + 255)/256, 256>>>(Wq, Wk, Wv, bq, bk, bv);
    cvt_tf32_kernel<<<(Ck*Ck/4 + 255)/256, 256>>>(Wo, wo32, Ck*Ck/4);
    cvt_tf32_kernel<<<(Ck*FF/4 + 255)/256, 256>>>(W1, w132, Ck*FF/4);
    cvt_tf32_kernel<<<(FF*Ck/4 + 255)/256, 256>>>(W2, w232, FF*Ck/4);

    // 1) ln1(x) -> h1 (tf32 bits)
    dim3 lnb(32, 8);
    ln_time_kernel<<<Bk*(Ck/32), lnb>>>(x, ln1_g, ln1_b, h1);

    // 2) qkv = h1 @ wpack + bpack -> tf32 bits
    tgemm_kernel<false,false,true><<<dim3(N3/128, MROWS/128), 256, TG_SMEM>>>(
        MROWS, N3, Ck, h1, wpack, bpack, nullptr, qkv);

    // 3) attention -> att (tf32 bits)
    flash_tc_kernel<<<Bk*Hk*(Tk/64), 128, FA_SMEM>>>(qkv, att);

    // 4) x2 = x + att @ Wo + bo   (fp32)
    tgemm_kernel<false,true,false><<<dim3(Ck/128, MROWS/128), 256, TG_SMEM>>>(
        MROWS, Ck, Ck, att, wo32, bo, x, x2);

    // 5) ln2(x2) -> h2 (tf32 bits)
    ln_time_kernel<<<Bk*(Ck/32), lnb>>>(x2, ln2_g, ln2_b, h2);

    // 6) ffn = relu(h2 @ W1 + b1) -> tf32 bits
    tgemm_kernel<true,false,true><<<dim3(FF/128, MROWS/128), 256, TG_SMEM>>>(
        MROWS, FF, Ck, h2, w132, b1, nullptr, ffn);

    // 7) out = x2 + ffn @ W2 + b2  (fp32)
    tgemm_kernel<false,true,false><<<dim3(Ck/128, MROWS/128), 256, TG_SMEM>>>(
        MROWS, Ck, FF, ffn, w232, b2, x2, out);
}

// round 9
// speedup vs baseline: 6.1724x; 1.5315x over previous
#include <cuda_runtime.h>
#include <cuda_fp16.h>
#include <math.h>
#include <stdint.h>

#define Bk 4
#define Tk 2048
#define Ck 1024
#define Hk 16
#define HSk 64
#define EPSk 1e-5f
#define MROWS (Bk*Tk)
#define N3 (3*Ck)
#define FF (4*Ck)

/* scratch (device globals; allocation is forbidden) */
__device__ __half g_h1[MROWS*Ck];
__device__ __half g_qkv[(size_t)MROWS*N3];
__device__ __half g_att[MROWS*Ck];
__device__ float  g_x2[MROWS*Ck];
__device__ __half g_h2[MROWS*Ck];
__device__ __half g_ffn[(size_t)MROWS*FF];
__device__ __half g_wpack[(size_t)N3*Ck];    /* [n=3072][k=1024] */
__device__ float  g_bpack[N3];
__device__ __half g_woT[Ck*Ck];              /* [n=1024][k=1024] */
__device__ __half g_w1T[(size_t)FF*Ck];      /* [n=4096][k=1024] */
__device__ __half g_w2T[(size_t)Ck*FF];      /* [n=1024][k=4096] */

/* ---------------- helpers ---------------- */
__device__ __forceinline__ void cp_async16(void* s, const void* g) {
    unsigned sa = (unsigned)__cvta_generic_to_shared(s);
    asm volatile("cp.async.cg.shared.global [%0], [%1], 16;" :: "r"(sa), "l"(g));
}
__device__ __forceinline__ void cp_commit() { asm volatile("cp.async.commit_group;"); }
__device__ __forceinline__ void cp_wait1() { asm volatile("cp.async.wait_group 1;" ::: "memory"); }

__device__ __forceinline__ void mma16816(float* c, const unsigned* a, const unsigned* b) {
    asm volatile("mma.sync.aligned.m16n8k16.row.col.f32.f16.f16.f32 {%0,%1,%2,%3}, {%4,%5,%6,%7}, {%8,%9}, {%0,%1,%2,%3};"
        : "+f"(c[0]), "+f"(c[1]), "+f"(c[2]), "+f"(c[3])
        : "r"(a[0]), "r"(a[1]), "r"(a[2]), "r"(a[3]), "r"(b[0]), "r"(b[1]));
}

/* ---------------- LayerNorm over time axis, emits half --------------------- */
__global__ void ln_time_kernel(const float* __restrict__ x,
                               const float* __restrict__ gam,
                               const float* __restrict__ beta,
                               __half* __restrict__ out) {
    int cb = blockIdx.x % (Ck/32);
    int b  = blockIdx.x / (Ck/32);
    int tx = threadIdx.x, ty = threadIdx.y;
    int c  = cb*32 + tx;
    const float* xp = x + (size_t)b*Tk*Ck + c;
    float s = 0.f, s2 = 0.f;
    for (int t = ty; t < Tk; t += 8) {
        float v = xp[(size_t)t*Ck];
        s += v;
        s2 += v*v;
    }
    __shared__ float ss[8][32];
    __shared__ float ss2[8][32];
    ss[ty][tx] = s;
    ss2[ty][tx] = s2;
    __syncthreads();
    if (ty == 0) {
        for (int i = 1; i < 8; i++) { s += ss[i][tx]; s2 += ss2[i][tx]; }
        float m   = s / (float)Tk;
        float var = (s2 - (float)Tk*m*m) / (float)(Tk-1);
        float inv = rsqrtf(var + EPSk);
        ss[0][tx]  = m;
        ss2[0][tx] = inv;
    }
    __syncthreads();
    float m = ss[0][tx], inv = ss2[0][tx];
    float gg = gam[c], bb = beta[c];
    __half* op = out + (size_t)b*Tk*Ck + c;
    for (int t = ty; t < Tk; t += 8) {
        op[(size_t)t*Ck] = __float2half_rn(gg * (xp[(size_t)t*Ck] - m) * inv + bb);
    }
}

/* ---------------- pack qkv weights: K-major [3072][1024] half -------------- */
__global__ void pack_qkvT_kernel(const float* __restrict__ Wq, const float* __restrict__ Wk,
                                 const float* __restrict__ Wv, const float* __restrict__ bq,
                                 const float* __restrict__ bkk, const float* __restrict__ bv) {
    int i = blockIdx.x * blockDim.x + threadIdx.x;
    if (i < N3*Ck) {
        int n = i >> 10;
        int c = i & 1023;
        int which = n >> 10;
        int nl = n & 1023;
        int h = nl >> 6;
        int d = nl & 63;
        const float* W = (which == 0) ? Wq : ((which == 1) ? Wk : Wv);
        g_wpack[(size_t)n*Ck + c] = __float2half_rn(W[((size_t)h*Ck + c)*HSk + d]);
    }
    if (i < Ck) {
        g_bpack[i]        = bq[i];
        g_bpack[Ck + i]   = bkk[i];
        g_bpack[2*Ck + i] = bv[i];
    }
}

/* ---------------- tiled transpose: dst[n][k] = half(src[k][n]) ------------- */
__global__ void transpose_h_kernel(const float* __restrict__ src, __half* __restrict__ dst,
                                   int K, int N) {
    __shared__ float t[32][33];
    int k0 = blockIdx.y*32, n0 = blockIdx.x*32;
    int tx = threadIdx.x, ty = threadIdx.y;
    for (int i = 0; i < 4; i++) {
        t[ty + 8*i][tx] = src[(size_t)(k0 + ty + 8*i)*N + n0 + tx];
    }
    __syncthreads();
    for (int i = 0; i < 4; i++) {
        dst[(size_t)(n0 + ty + 8*i)*K + k0 + tx] = __float2half_rn(t[tx][ty + 8*i]);
    }
}

/* ---------------- fp16 tensor GEMM: C = A[M,K] x Bt[N,K]^T ----------------- */
/* 256 threads, tile 128x128, BK=32, 3-stage cp.async, pitch 40 halfs.        */
#define GP 40
#define GSTG (128*GP)               /* halfs per matrix per stage */
#define G_SMEM (3*2*GSTG*2)         /* bytes */

template<bool RELU, bool RES, bool OHALF>
__global__ __launch_bounds__(256, 2)
void hgemm_kernel(int M, int N, int K,
                  const __half* __restrict__ A,
                  const __half* __restrict__ Bt,
                  const float* __restrict__ bias,
                  const float* __restrict__ res,
                  float* __restrict__ Cf,
                  __half* __restrict__ Ch) {
    extern __shared__ __half smh[];
    int tid  = threadIdx.x;
    int lane = tid & 31;
    int warp = tid >> 5;
    int g = lane >> 2;
    int c = lane & 3;
    int warpM = warp & 1;
    int warpN = warp >> 1;
    int bm0 = blockIdx.y * 128;
    int bn0 = blockIdx.x * 128;

    float acc[4][4][4];
    for (int mt = 0; mt < 4; mt++) {
        for (int nt = 0; nt < 4; nt++) {
            acc[mt][nt][0] = 0.f; acc[mt][nt][1] = 0.f;
            acc[mt][nt][2] = 0.f; acc[mt][nt][3] = 0.f;
        }
    }

    const __half* Ag = A  + (size_t)bm0 * K;
    const __half* Bg = Bt + (size_t)bn0 * K;
    int nk = K / 32;

    /* stage loader: buf in 0..2 */
    auto load_stage = [&](int st, int buf) {
        __half* As = smh + buf*2*GSTG;
        __half* Bs = As + GSTG;
        int k0 = st * 32;
        for (int i = 0; i < 2; i++) {
            int id = i*256 + tid;
            int row = id >> 2;
            int c8 = id & 3;
            cp_async16(As + row*GP + c8*8, Ag + (size_t)row*K + k0 + c8*8);
        }
        for (int i = 0; i < 2; i++) {
            int id = i*256 + tid;
            int row = id >> 2;
            int c8 = id & 3;
            cp_async16(Bs + row*GP + c8*8, Bg + (size_t)row*K + k0 + c8*8);
        }
    };

    load_stage(0, 0); cp_commit();
    load_stage(1, 1); cp_commit();

    for (int t = 0; t < nk; t++) {
        cp_wait1();
        __syncthreads();
        if (t + 2 < nk) { load_stage(t + 2, (t + 2) % 3); }
        cp_commit();
        const __half* As = smh + (t % 3)*2*GSTG;
        const __half* Bs = As + GSTG;
        for (int ks = 0; ks < 2; ks++) {
            int kc = ks * 16;
            unsigned af[4][4], bf[4][2];
            for (int mt = 0; mt < 4; mt++) {
                int r0 = warpM*64 + mt*16 + g;
                af[mt][0] = *(const unsigned*)&As[r0*GP + kc + 2*c];
                af[mt][1] = *(const unsigned*)&As[(r0+8)*GP + kc + 2*c];
                af[mt][2] = *(const unsigned*)&As[r0*GP + kc + 2*c + 8];
                af[mt][3] = *(const unsigned*)&As[(r0+8)*GP + kc + 2*c + 8];
            }
            for (int nt = 0; nt < 4; nt++) {
                int n0 = warpN*32 + nt*8 + g;
                bf[nt][0] = *(const unsigned*)&Bs[n0*GP + kc + 2*c];
                bf[nt][1] = *(const unsigned*)&Bs[n0*GP + kc + 2*c + 8];
            }
            for (int mt = 0; mt < 4; mt++) {
                for (int nt = 0; nt < 4; nt++) {
                    mma16816(acc[mt][nt], af[mt], bf[nt]);
                }
            }
        }
        __syncthreads();
    }

    /* epilogue */
    for (int mt = 0; mt < 4; mt++) {
        for (int nt = 0; nt < 4; nt++) {
            for (int hh = 0; hh < 2; hh++) {
                int row = bm0 + warpM*64 + mt*16 + g + hh*8;
                int col = bn0 + warpN*32 + nt*8 + 2*c;
                float v0 = acc[mt][nt][hh*2+0] + bias[col];
                float v1 = acc[mt][nt][hh*2+1] + bias[col+1];
                if (RES) {
                    v0 += res[(size_t)row*N + col];
                    v1 += res[(size_t)row*N + col + 1];
                }
                if (RELU) { v0 = fmaxf(v0, 0.f); v1 = fmaxf(v1, 0.f); }
                if (OHALF) {
                    *(__half2*)&Ch[(size_t)row*N + col] = __floats2half2_rn(v0, v1);
                } else {
                    *(float2*)&Cf[(size_t)row*N + col] = make_float2(v0, v1);
                }
            }
        }
    }
}

/* ---------------- flash attention: fp16 mma, fp32 softmax, causal ---------- */
#define FP 72
#define FA_SMEM (3*64*FP*2)

__global__ __launch_bounds__(128, 4)
void flash_h_kernel(const __half* __restrict__ qkv, __half* __restrict__ att) {
    extern __shared__ __half smh[];
    __half* Qs = smh;            /* [64][FP], reused as Ps */
    __half* Ks = Qs + 64*FP;     /* [64][FP]  [key][d] */
    __half* VT = Ks + 64*FP;     /* [64][FP]  [d][key] */
    __half* Ps = Qs;

    int tid  = threadIdx.x;
    int lane = tid & 31;
    int warp = tid >> 5;
    int gq = lane >> 2;
    int cq = lane & 3;

    const int ntiles = Tk / 64;
    int qt = (ntiles - 1) - (blockIdx.x % ntiles);
    int h  = (blockIdx.x / ntiles) % Hk;
    int b  =  blockIdx.x / (ntiles * Hk);
    int q0 = qt * 64;
    const __half* qbase = qkv + (size_t)b*Tk*N3 + h*HSk;
    const __half* kbase = qbase + Ck;
    const __half* vbase = qbase + 2*Ck;

    /* stage Q: 64 rows x 64 d, uint4 = 8 halfs */
    for (int i = 0; i < 4; i++) {
        int id = i*128 + tid;
        int r = id >> 3;
        int c8 = id & 7;
        *(uint4*)&Qs[r*FP + c8*8] = *(const uint4*)(qbase + (size_t)(q0 + r)*N3 + c8*8);
    }
    __syncthreads();

    int rl = warp*16 + gq;
    unsigned qa[4][4];
    for (int ks = 0; ks < 4; ks++) {
        int kc = ks*16 + 2*cq;
        qa[ks][0] = *(const unsigned*)&Qs[rl*FP + kc];
        qa[ks][1] = *(const unsigned*)&Qs[(rl+8)*FP + kc];
        qa[ks][2] = *(const unsigned*)&Qs[rl*FP + kc + 8];
        qa[ks][3] = *(const unsigned*)&Qs[(rl+8)*FP + kc + 8];
    }

    float m0 = -1e30f, m1 = -1e30f, l0 = 0.f, l1 = 0.f;
    float o[8][4];
    for (int nt = 0; nt < 8; nt++) {
        o[nt][0] = 0.f; o[nt][1] = 0.f; o[nt][2] = 0.f; o[nt][3] = 0.f;
    }

    int row0 = q0 + rl;
    int row1 = row0 + 8;
    int nkb = q0/64 + 1;

    for (int kb = 0; kb < nkb; kb++) {
        __syncthreads();
        /* stage K [key][d] */
        for (int i = 0; i < 4; i++) {
            int id = i*128 + tid;
            int r = id >> 3;
            int c8 = id & 7;
            *(uint4*)&Ks[r*FP + c8*8] = *(const uint4*)(kbase + (size_t)(kb*64 + r)*N3 + c8*8);
        }
        /* stage V transposed: VT[d][key], half2 over key pairs */
        for (int i = 0; i < 2; i++) {
            int id = i*128 + tid;
            int kp = id & 31;            /* key pair: keys 2kp, 2kp+1 */
            int dg = id >> 5;            /* d group 0..7 */
            int d0 = dg*8;
            const __half* v0p = vbase + (size_t)(kb*64 + 2*kp)*N3 + d0;
            const __half* v1p = v0p + N3;
            uint4 va = *(const uint4*)v0p;
            uint4 vb = *(const uint4*)v1p;
            const __half* pa = (const __half*)&va;
            const __half* pb = (const __half*)&vb;
            for (int jj = 0; jj < 8; jj++) {
                *(__half2*)&VT[(d0+jj)*FP + 2*kp] = __halves2half2(pa[jj], pb[jj]);
            }
        }
        __syncthreads();

        /* S = Q K^T */
        float s[8][4];
        for (int nt = 0; nt < 8; nt++) {
            s[nt][0] = 0.f; s[nt][1] = 0.f; s[nt][2] = 0.f; s[nt][3] = 0.f;
        }
        for (int ks = 0; ks < 4; ks++) {
            int kc = ks*16 + 2*cq;
            for (int nt = 0; nt < 8; nt++) {
                unsigned bf[2];
                int n0 = nt*8 + gq;
                bf[0] = *(const unsigned*)&Ks[n0*FP + kc];
                bf[1] = *(const unsigned*)&Ks[n0*FP + kc + 8];
                mma16816(s[nt], qa[ks], bf);
            }
        }

        /* mask + scale + online softmax (fp32) */
        float rmax0 = -1e30f, rmax1 = -1e30f;
        for (int nt = 0; nt < 8; nt++) {
            int col = kb*64 + nt*8 + 2*cq;
            s[nt][0] = (col   <= row0) ? s[nt][0]*0.03125f : -1e30f;
            s[nt][1] = (col+1 <= row0) ? s[nt][1]*0.03125f : -1e30f;
            s[nt][2] = (col   <= row1) ? s[nt][2]*0.03125f : -1e30f;
            s[nt][3] = (col+1 <= row1) ? s[nt][3]*0.03125f : -1e30f;
            rmax0 = fmaxf(rmax0, fmaxf(s[nt][0], s[nt][1]));
            rmax1 = fmaxf(rmax1, fmaxf(s[nt][2], s[nt][3]));
        }
        rmax0 = fmaxf(rmax0, __shfl_xor_sync(0xffffffffu, rmax0, 1));
        rmax0 = fmaxf(rmax0, __shfl_xor_sync(0xffffffffu, rmax0, 2));
        rmax1 = fmaxf(rmax1, __shfl_xor_sync(0xffffffffu, rmax1, 1));
        rmax1 = fmaxf(rmax1, __shfl_xor_sync(0xffffffffu, rmax1, 2));
        float mn0 = fmaxf(m0, rmax0);
        float mn1 = fmaxf(m1, rmax1);
        float corr0 = __expf(m0 - mn0);
        float corr1 = __expf(m1 - mn1);
        float ps0 = 0.f, ps1 = 0.f;
        for (int nt = 0; nt < 8; nt++) {
            float p0 = __expf(s[nt][0] - mn0);
            float p1 = __expf(s[nt][1] - mn0);
            float p2 = __expf(s[nt][2] - mn1);
            float p3 = __expf(s[nt][3] - mn1);
            ps0 += p0 + p1;
            ps1 += p2 + p3;
            int cl = nt*8 + 2*cq;
            *(__half2*)&Ps[rl*FP + cl]     = __floats2half2_rn(p0, p1);
            *(__half2*)&Ps[(rl+8)*FP + cl] = __floats2half2_rn(p2, p3);
        }
        ps0 += __shfl_xor_sync(0xffffffffu, ps0, 1);
        ps0 += __shfl_xor_sync(0xffffffffu, ps0, 2);
        ps1 += __shfl_xor_sync(0xffffffffu, ps1, 1);
        ps1 += __shfl_xor_sync(0xffffffffu, ps1, 2);
        l0 = l0*corr0 + ps0;
        l1 = l1*corr1 + ps1;
        m0 = mn0;
        m1 = mn1;
        for (int nt = 0; nt < 8; nt++) {
            o[nt][0] *= corr0; o[nt][1] *= corr0;
            o[nt][2] *= corr1; o[nt][3] *= corr1;
        }
        __syncwarp();

        /* O += P V : A = P [row][key], B = VT [d][key] (col-major over key) */
        for (int ks = 0; ks < 4; ks++) {
            int kc = ks*16 + 2*cq;
            unsigned pa[4];
            pa[0] = *(const unsigned*)&Ps[rl*FP + kc];
            pa[1] = *(const unsigned*)&Ps[(rl+8)*FP + kc];
            pa[2] = *(const unsigned*)&Ps[rl*FP + kc + 8];
            pa[3] = *(const unsigned*)&Ps[(rl+8)*FP + kc + 8];
            for (int nt = 0; nt < 8; nt++) {
                unsigned bf[2];
                int n0 = nt*8 + gq;
                bf[0] = *(const unsigned*)&VT[n0*FP + kc];
                bf[1] = *(const unsigned*)&VT[n0*FP + kc + 8];
                mma16816(o[nt], pa, bf);
            }
        }
    }

    float inv0 = 1.f / l0;
    float inv1 = 1.f / l1;
    __half* ob0 = att + (size_t)(b*Tk + row0)*Ck + h*HSk;
    __half* ob1 = att + (size_t)(b*Tk + row1)*Ck + h*HSk;
    for (int nt = 0; nt < 8; nt++) {
        int cl = nt*8 + 2*cq;
        *(__half2*)&ob0[cl] = __floats2half2_rn(o[nt][0]*inv0, o[nt][1]*inv0);
        *(__half2*)&ob1[cl] = __floats2half2_rn(o[nt][2]*inv1, o[nt][3]*inv1);
    }
}

/* --------------------------------------------------------------------------- */
extern "C" void kernel_launch(void* const* d_in, const int* in_sizes, int n_in,
                              void* d_out, int out_size) {
    const float* x     = (const float*)d_in[0];
    const float* ln1_g = (const float*)d_in[1];
    const float* ln1_b = (const float*)d_in[2];
    const float* ln2_g = (const float*)d_in[3];
    const float* ln2_b = (const float*)d_in[4];
    const float* Wq    = (const float*)d_in[5];
    const float* bq    = (const float*)d_in[6];
    const float* Wk    = (const float*)d_in[7];
    const float* bk    = (const float*)d_in[8];
    const float* Wv    = (const float*)d_in[9];
    const float* bv    = (const float*)d_in[10];
    const float* Wo    = (const float*)d_in[11];
    const float* bo    = (const float*)d_in[12];
    const float* W1    = (const float*)d_in[13];
    const float* b1    = (const float*)d_in[14];
    const float* W2    = (const float*)d_in[15];
    const float* b2    = (const float*)d_in[16];
    float* out = (float*)d_out;

    __half *h1, *qkv, *att, *h2, *ffn, *wpack, *woT, *w1T, *w2T;
    float *x2, *bpack;
    cudaGetSymbolAddress((void**)&h1,    g_h1);
    cudaGetSymbolAddress((void**)&qkv,   g_qkv);
    cudaGetSymbolAddress((void**)&att,   g_att);
    cudaGetSymbolAddress((void**)&x2,    g_x2);
    cudaGetSymbolAddress((void**)&h2,    g_h2);
    cudaGetSymbolAddress((void**)&ffn,   g_ffn);
    cudaGetSymbolAddress((void**)&wpack, g_wpack);
    cudaGetSymbolAddress((void**)&bpack, g_bpack);
    cudaGetSymbolAddress((void**)&woT,   g_woT);
    cudaGetSymbolAddress((void**)&w1T,   g_w1T);
    cudaGetSymbolAddress((void**)&w2T,   g_w2T);

    cudaFuncSetAttribute(hgemm_kernel<false,false,true>,  cudaFuncAttributeMaxDynamicSharedMemorySize, G_SMEM);
    cudaFuncSetAttribute(hgemm_kernel<false,true,false>,  cudaFuncAttributeMaxDynamicSharedMemorySize, G_SMEM);
    cudaFuncSetAttribute(hgemm_kernel<true,false,true>,   cudaFuncAttributeMaxDynamicSharedMemorySize, G_SMEM);
    cudaFuncSetAttribute(flash_h_kernel, cudaFuncAttributeMaxDynamicSharedMemorySize, FA_SMEM);

    /* weights -> K-major half */
    pack_qkvT_kernel<<<(N3*Ck + 255)/256, 256>>>(Wq, Wk, Wv, bq, bk, bv);
    dim3 tb(32, 8);
    transpose_h_kernel<<<dim3(Ck/32, Ck/32), tb>>>(Wo, woT, Ck, Ck);
    transpose_h_kernel<<<dim3(FF/32, Ck/32), tb>>>(W1, w1T, Ck, FF);
    transpose_h_kernel<<<dim3(Ck/32, FF/32), tb>>>(W2, w2T, FF, Ck);

    dim3 lnb(32, 8);
    ln_time_kernel<<<Bk*(Ck/32), lnb>>>(x, ln1_g, ln1_b, h1);

    /* qkv = h1 @ Wqkv + b  (half out) */
    hgemm_kernel<false,false,true><<<dim3(N3/128, MROWS/128), 256, G_SMEM>>>(
        MROWS, N3, Ck, h1, wpack, bpack, (const float*)0, (float*)0, qkv);

    flash_h_kernel<<<Bk*Hk*(Tk/64), 128, FA_SMEM>>>(qkv, att);

    /* x2 = x + att @ Wo + bo  (fp32 out) */
    hgemm_kernel<false,true,false><<<dim3(Ck/128, MROWS/128), 256, G_SMEM>>>(
        MROWS, Ck, Ck, att, woT, bo, x, x2, (__half*)0);

    ln_time_kernel<<<Bk*(Ck/32), lnb>>>(x2, ln2_g, ln2_b, h2);

    /* ffn = relu(h2 @ W1 + b1)  (half out) */
    hgemm_kernel<true,false,true><<<dim3(FF/128, MROWS/128), 256, G_SMEM>>>(
        MROWS, FF, Ck, h2, w1T, b1, (const float*)0, (float*)0, ffn);

    /* out = x2 + ffn @ W2 + b2  (fp32 out) */
    hgemm_kernel<false,true,false><<<dim3(Ck/128, MROWS/128), 256, G_SMEM>>>(
        MROWS, Ck, FF, ffn, w2T, b2, x2, out, (__half*)0);
}

// round 10
// speedup vs baseline: 7.0605x; 1.1439x over previous
#include <cuda_runtime.h>
#include <cuda_fp16.h>
#include <math.h>
#include <stdint.h>

#define Bk 4
#define Tk 2048
#define Ck 1024
#define Hk 16
#define HSk 64
#define EPSk 1e-5f
#define MROWS (Bk*Tk)
#define N3 (3*Ck)
#define FF (4*Ck)

/* scratch (device globals; allocation is forbidden) */
__device__ __half g_h1[MROWS*Ck];
__device__ __half g_qkv[(size_t)MROWS*N3];
__device__ __half g_att[MROWS*Ck];
__device__ float  g_x2[MROWS*Ck];
__device__ __half g_h2[MROWS*Ck];
__device__ __half g_ffn[(size_t)MROWS*FF];
__device__ __half g_wpack[(size_t)N3*Ck];
__device__ float  g_bpack[N3];
__device__ __half g_woT[Ck*Ck];
__device__ __half g_w1T[(size_t)FF*Ck];
__device__ __half g_w2T[(size_t)Ck*FF];

/* ---------------- helpers ---------------- */
__device__ __forceinline__ void cp_async16(void* s, const void* g) {
    unsigned sa = (unsigned)__cvta_generic_to_shared(s);
    asm volatile("cp.async.cg.shared.global [%0], [%1], 16;" :: "r"(sa), "l"(g));
}
__device__ __forceinline__ void cp_commit() { asm volatile("cp.async.commit_group;"); }
__device__ __forceinline__ void cp_wait1() { asm volatile("cp.async.wait_group 1;" ::: "memory"); }

__device__ __forceinline__ uint32_t smem_u32(const void* p) {
    return (uint32_t)__cvta_generic_to_shared(p);
}
__device__ __forceinline__ void mma16816(float* c, const unsigned* a, const unsigned* b) {
    asm volatile("mma.sync.aligned.m16n8k16.row.col.f32.f16.f16.f32 {%0,%1,%2,%3}, {%4,%5,%6,%7}, {%8,%9}, {%0,%1,%2,%3};"
        : "+f"(c[0]), "+f"(c[1]), "+f"(c[2]), "+f"(c[3])
        : "r"(a[0]), "r"(a[1]), "r"(a[2]), "r"(a[3]), "r"(b[0]), "r"(b[1]));
}
__device__ __forceinline__ void ldsm4(unsigned* r, uint32_t addr) {
    asm volatile("ldmatrix.sync.aligned.m8n8.x4.shared.b16 {%0,%1,%2,%3}, [%4];"
        : "=r"(r[0]), "=r"(r[1]), "=r"(r[2]), "=r"(r[3]) : "r"(addr));
}
__device__ __forceinline__ void ldsm4t(unsigned* r, uint32_t addr) {
    asm volatile("ldmatrix.sync.aligned.m8n8.x4.trans.shared.b16 {%0,%1,%2,%3}, [%4];"
        : "=r"(r[0]), "=r"(r[1]), "=r"(r[2]), "=r"(r[3]) : "r"(addr));
}

/* ---------------- LayerNorm over time axis, emits half --------------------- */
__global__ void ln_time_kernel(const float* __restrict__ x,
                               const float* __restrict__ gam,
                               const float* __restrict__ beta,
                               __half* __restrict__ out) {
    int cb = blockIdx.x % (Ck/32);
    int b  = blockIdx.x / (Ck/32);
    int tx = threadIdx.x, ty = threadIdx.y;
    int c  = cb*32 + tx;
    const float* xp = x + (size_t)b*Tk*Ck + c;
    float s = 0.f, s2 = 0.f;
    for (int t = ty; t < Tk; t += 8) {
        float v = xp[(size_t)t*Ck];
        s += v;
        s2 += v*v;
    }
    __shared__ float ss[8][32];
    __shared__ float ss2[8][32];
    ss[ty][tx] = s;
    ss2[ty][tx] = s2;
    __syncthreads();
    if (ty == 0) {
        for (int i = 1; i < 8; i++) { s += ss[i][tx]; s2 += ss2[i][tx]; }
        float m   = s / (float)Tk;
        float var = (s2 - (float)Tk*m*m) / (float)(Tk-1);
        float inv = rsqrtf(var + EPSk);
        ss[0][tx]  = m;
        ss2[0][tx] = inv;
    }
    __syncthreads();
    float m = ss[0][tx], inv = ss2[0][tx];
    float gg = gam[c], bb = beta[c];
    __half* op = out + (size_t)b*Tk*Ck + c;
    for (int t = ty; t < Tk; t += 8) {
        op[(size_t)t*Ck] = __float2half_rn(gg * (xp[(size_t)t*Ck] - m) * inv + bb);
    }
}

/* ---------------- pack qkv weights: K-major [3072][1024] half -------------- */
__global__ void pack_qkvT_kernel(const float* __restrict__ Wq, const float* __restrict__ Wk,
                                 const float* __restrict__ Wv, const float* __restrict__ bq,
                                 const float* __restrict__ bkk, const float* __restrict__ bv) {
    int i = blockIdx.x * blockDim.x + threadIdx.x;
    if (i < N3*Ck) {
        int n = i >> 10;
        int c = i & 1023;
        int which = n >> 10;
        int nl = n & 1023;
        int h = nl >> 6;
        int d = nl & 63;
        const float* W = (which == 0) ? Wq : ((which == 1) ? Wk : Wv);
        g_wpack[(size_t)n*Ck + c] = __float2half_rn(W[((size_t)h*Ck + c)*HSk + d]);
    }
    if (i < Ck) {
        g_bpack[i]        = bq[i];
        g_bpack[Ck + i]   = bkk[i];
        g_bpack[2*Ck + i] = bv[i];
    }
}

/* ---------------- tiled transpose: dst[n][k] = half(src[k][n]) ------------- */
__global__ void transpose_h_kernel(const float* __restrict__ src, __half* __restrict__ dst,
                                   int K, int N) {
    __shared__ float t[32][33];
    int k0 = blockIdx.y*32, n0 = blockIdx.x*32;
    int tx = threadIdx.x, ty = threadIdx.y;
    for (int i = 0; i < 4; i++) {
        t[ty + 8*i][tx] = src[(size_t)(k0 + ty + 8*i)*N + n0 + tx];
    }
    __syncthreads();
    for (int i = 0; i < 4; i++) {
        dst[(size_t)(n0 + ty + 8*i)*K + k0 + tx] = __float2half_rn(t[tx][ty + 8*i]);
    }
}

/* ---------------- fp16 tensor GEMM: C = A[M,K] x Bt[N,K]^T ----------------- */
#define GP 40
#define GSTG (128*GP)
#define G_SMEM (3*2*GSTG*2)

template<bool RELU, bool RES, bool OHALF>
__global__ __launch_bounds__(256, 2)
void hgemm_kernel(int M, int N, int K,
                  const __half* __restrict__ A,
                  const __half* __restrict__ Bt,
                  const float* __restrict__ bias,
                  const float* __restrict__ res,
                  float* __restrict__ Cf,
                  __half* __restrict__ Ch) {
    extern __shared__ __half smh[];
    int tid  = threadIdx.x;
    int lane = tid & 31;
    int warp = tid >> 5;
    int g = lane >> 2;
    int c = lane & 3;
    int warpM = warp & 1;
    int warpN = warp >> 1;
    int bm0 = blockIdx.y * 128;
    int bn0 = blockIdx.x * 128;

    float acc[4][4][4];
    for (int mt = 0; mt < 4; mt++) {
        for (int nt = 0; nt < 4; nt++) {
            acc[mt][nt][0] = 0.f; acc[mt][nt][1] = 0.f;
            acc[mt][nt][2] = 0.f; acc[mt][nt][3] = 0.f;
        }
    }

    const __half* Ag = A  + (size_t)bm0 * K;
    const __half* Bg = Bt + (size_t)bn0 * K;
    int nk = K / 32;

    auto load_stage = [&](int st, int buf) {
        __half* As = smh + buf*2*GSTG;
        __half* Bs = As + GSTG;
        int k0 = st * 32;
        for (int i = 0; i < 2; i++) {
            int id = i*256 + tid;
            int row = id >> 2;
            int c8 = id & 3;
            cp_async16(As + row*GP + c8*8, Ag + (size_t)row*K + k0 + c8*8);
        }
        for (int i = 0; i < 2; i++) {
            int id = i*256 + tid;
            int row = id >> 2;
            int c8 = id & 3;
            cp_async16(Bs + row*GP + c8*8, Bg + (size_t)row*K + k0 + c8*8);
        }
    };

    load_stage(0, 0); cp_commit();
    load_stage(1, 1); cp_commit();

    int la = lane & 15;
    int lko = (lane >> 4) * 8;          /* k offset for A/P style frags */
    int lnb = (lane & 7) + ((lane & 16) >> 1);  /* n row for B style frags */
    int lkb = lane & 8;                 /* k offset for B style frags */

    for (int t = 0; t < nk; t++) {
        cp_wait1();
        __syncthreads();
        if (t + 2 < nk) { load_stage(t + 2, (t + 2) % 3); }
        cp_commit();
        const __half* As = smh + (t % 3)*2*GSTG;
        const __half* Bs = As + GSTG;
        for (int ks = 0; ks < 2; ks++) {
            int kc = ks * 16;
            unsigned af[4][4], bf[4][2];
            for (int mt = 0; mt < 4; mt++) {
                int r0 = warpM*64 + mt*16;
                ldsm4(af[mt], smem_u32(&As[(r0 + la)*GP + kc + lko]));
            }
            for (int pr = 0; pr < 2; pr++) {
                int n0 = warpN*32 + pr*16;
                unsigned rr[4];
                ldsm4(rr, smem_u32(&Bs[(n0 + lnb)*GP + kc + lkb]));
                bf[pr*2][0] = rr[0]; bf[pr*2][1] = rr[1];
                bf[pr*2+1][0] = rr[2]; bf[pr*2+1][1] = rr[3];
            }
            for (int mt = 0; mt < 4; mt++) {
                for (int nt = 0; nt < 4; nt++) {
                    mma16816(acc[mt][nt], af[mt], bf[nt]);
                }
            }
        }
        __syncthreads();
    }

    for (int mt = 0; mt < 4; mt++) {
        for (int nt = 0; nt < 4; nt++) {
            for (int hh = 0; hh < 2; hh++) {
                int row = bm0 + warpM*64 + mt*16 + g + hh*8;
                int col = bn0 + warpN*32 + nt*8 + 2*c;
                float v0 = acc[mt][nt][hh*2+0] + bias[col];
                float v1 = acc[mt][nt][hh*2+1] + bias[col+1];
                if (RES) {
                    v0 += res[(size_t)row*N + col];
                    v1 += res[(size_t)row*N + col + 1];
                }
                if (RELU) { v0 = fmaxf(v0, 0.f); v1 = fmaxf(v1, 0.f); }
                if (OHALF) {
                    *(__half2*)&Ch[(size_t)row*N + col] = __floats2half2_rn(v0, v1);
                } else {
                    *(float2*)&Cf[(size_t)row*N + col] = make_float2(v0, v1);
                }
            }
        }
    }
}

/* ---------------- flash attention: fp16 mma + ldmatrix, causal ------------- */
#define FP 72
#define FA_SMEM (3*64*FP*2)

__global__ __launch_bounds__(128, 4)
void flash_h_kernel(const __half* __restrict__ qkv, __half* __restrict__ att) {
    extern __shared__ __half smh[];
    __half* Qs = smh;            /* [64][FP], reused as Ps */
    __half* Ks = Qs + 64*FP;     /* [64][FP]  [key][d] */
    __half* Vs = Ks + 64*FP;     /* [64][FP]  [key][d] */
    __half* Ps = Qs;

    int tid  = threadIdx.x;
    int lane = tid & 31;
    int warp = tid >> 5;
    int gq = lane >> 2;
    int cq = lane & 3;

    const int ntiles = Tk / 64;
    int qt = (ntiles - 1) - (blockIdx.x % ntiles);
    int h  = (blockIdx.x / ntiles) % Hk;
    int b  =  blockIdx.x / (ntiles * Hk);
    int q0 = qt * 64;
    const __half* qbase = qkv + (size_t)b*Tk*N3 + h*HSk;
    const __half* kbase = qbase + Ck;
    const __half* vbase = qbase + 2*Ck;

    for (int i = 0; i < 4; i++) {
        int id = i*128 + tid;
        int r = id >> 3;
        int c8 = id & 7;
        *(uint4*)&Qs[r*FP + c8*8] = *(const uint4*)(qbase + (size_t)(q0 + r)*N3 + c8*8);
    }
    __syncthreads();

    int la = lane & 15;
    int lko = (lane >> 4) * 8;
    int lnb = (lane & 7) + ((lane & 16) >> 1);
    int lkb = lane & 8;
    int ldo = (lane & 16) >> 1;   /* d offset for V trans frags */

    int rl = warp*16 + gq;
    unsigned qa[4][4];
    for (int ks = 0; ks < 4; ks++) {
        ldsm4(qa[ks], smem_u32(&Qs[(warp*16 + la)*FP + ks*16 + lko]));
    }

    float m0 = -1e30f, m1 = -1e30f, l0 = 0.f, l1 = 0.f;
    float o[8][4];
    for (int nt = 0; nt < 8; nt++) {
        o[nt][0] = 0.f; o[nt][1] = 0.f; o[nt][2] = 0.f; o[nt][3] = 0.f;
    }

    int row0 = q0 + rl;
    int row1 = row0 + 8;
    int nkb = q0/64 + 1;

    for (int kb = 0; kb < nkb; kb++) {
        __syncthreads();
        for (int i = 0; i < 4; i++) {
            int id = i*128 + tid;
            int r = id >> 3;
            int c8 = id & 7;
            *(uint4*)&Ks[r*FP + c8*8] = *(const uint4*)(kbase + (size_t)(kb*64 + r)*N3 + c8*8);
            *(uint4*)&Vs[r*FP + c8*8] = *(const uint4*)(vbase + (size_t)(kb*64 + r)*N3 + c8*8);
        }
        __syncthreads();

        /* S = Q K^T */
        float s[8][4];
        for (int nt = 0; nt < 8; nt++) {
            s[nt][0] = 0.f; s[nt][1] = 0.f; s[nt][2] = 0.f; s[nt][3] = 0.f;
        }
        for (int ks = 0; ks < 4; ks++) {
            int kc = ks*16;
            unsigned bf[8][2];
            for (int pr = 0; pr < 4; pr++) {
                unsigned rr[4];
                ldsm4(rr, smem_u32(&Ks[(pr*16 + lnb)*FP + kc + lkb]));
                bf[pr*2][0] = rr[0]; bf[pr*2][1] = rr[1];
                bf[pr*2+1][0] = rr[2]; bf[pr*2+1][1] = rr[3];
            }
            for (int nt = 0; nt < 8; nt++) {
                mma16816(s[nt], qa[ks], bf[nt]);
            }
        }

        /* mask + scale + online softmax (fp32) */
        float rmax0 = -1e30f, rmax1 = -1e30f;
        for (int nt = 0; nt < 8; nt++) {
            int col = kb*64 + nt*8 + 2*cq;
            s[nt][0] = (col   <= row0) ? s[nt][0]*0.03125f : -1e30f;
            s[nt][1] = (col+1 <= row0) ? s[nt][1]*0.03125f : -1e30f;
            s[nt][2] = (col   <= row1) ? s[nt][2]*0.03125f : -1e30f;
            s[nt][3] = (col+1 <= row1) ? s[nt][3]*0.03125f : -1e30f;
            rmax0 = fmaxf(rmax0, fmaxf(s[nt][0], s[nt][1]));
            rmax1 = fmaxf(rmax1, fmaxf(s[nt][2], s[nt][3]));
        }
        rmax0 = fmaxf(rmax0, __shfl_xor_sync(0xffffffffu, rmax0, 1));
        rmax0 = fmaxf(rmax0, __shfl_xor_sync(0xffffffffu, rmax0, 2));
        rmax1 = fmaxf(rmax1, __shfl_xor_sync(0xffffffffu, rmax1, 1));
        rmax1 = fmaxf(rmax1, __shfl_xor_sync(0xffffffffu, rmax1, 2));
        float mn0 = fmaxf(m0, rmax0);
        float mn1 = fmaxf(m1, rmax1);
        float corr0 = __expf(m0 - mn0);
        float corr1 = __expf(m1 - mn1);
        float ps0 = 0.f, ps1 = 0.f;
        for (int nt = 0; nt < 8; nt++) {
            float p0 = __expf(s[nt][0] - mn0);
            float p1 = __expf(s[nt][1] - mn0);
            float p2 = __expf(s[nt][2] - mn1);
            float p3 = __expf(s[nt][3] - mn1);
            ps0 += p0 + p1;
            ps1 += p2 + p3;
            int cl = nt*8 + 2*cq;
            *(__half2*)&Ps[rl*FP + cl]     = __floats2half2_rn(p0, p1);
            *(__half2*)&Ps[(rl+8)*FP + cl] = __floats2half2_rn(p2, p3);
        }
        ps0 += __shfl_xor_sync(0xffffffffu, ps0, 1);
        ps0 += __shfl_xor_sync(0xffffffffu, ps0, 2);
        ps1 += __shfl_xor_sync(0xffffffffu, ps1, 1);
        ps1 += __shfl_xor_sync(0xffffffffu, ps1, 2);
        l0 = l0*corr0 + ps0;
        l1 = l1*corr1 + ps1;
        m0 = mn0;
        m1 = mn1;
        for (int nt = 0; nt < 8; nt++) {
            o[nt][0] *= corr0; o[nt][1] *= corr0;
            o[nt][2] *= corr1; o[nt][3] *= corr1;
        }
        __syncwarp();

        /* O += P V : A = P [row][key] via ldmatrix, B = V [key][d] via trans */
        for (int ks = 0; ks < 4; ks++) {
            int kc = ks*16;
            unsigned pa[4];
            ldsm4(pa, smem_u32(&Ps[(warp*16 + la)*FP + kc + lko]));
            for (int pr = 0; pr < 4; pr++) {
                unsigned rr[4];
                ldsm4t(rr, smem_u32(&Vs[(kc + la)*FP + pr*16 + ldo]));
                mma16816(o[pr*2],     pa, rr + 0);
                mma16816(o[pr*2 + 1], pa, rr + 2);
            }
        }
    }

    float inv0 = 1.f / l0;
    float inv1 = 1.f / l1;
    __half* ob0 = att + (size_t)(b*Tk + row0)*Ck + h*HSk;
    __half* ob1 = att + (size_t)(b*Tk + row1)*Ck + h*HSk;
    for (int nt = 0; nt < 8; nt++) {
        int cl = nt*8 + 2*cq;
        *(__half2*)&ob0[cl] = __floats2half2_rn(o[nt][0]*inv0, o[nt][1]*inv0);
        *(__half2*)&ob1[cl] = __floats2half2_rn(o[nt][2]*inv1, o[nt][3]*inv1);
    }
}

/* --------------------------------------------------------------------------- */
extern "C" void kernel_launch(void* const* d_in, const int* in_sizes, int n_in,
                              void* d_out, int out_size) {
    const float* x     = (const float*)d_in[0];
    const float* ln1_g = (const float*)d_in[1];
    const float* ln1_b = (const float*)d_in[2];
    const float* ln2_g = (const float*)d_in[3];
    const float* ln2_b = (const float*)d_in[4];
    const float* Wq    = (const float*)d_in[5];
    const float* bq    = (const float*)d_in[6];
    const float* Wk    = (const float*)d_in[7];
    const float* bk    = (const float*)d_in[8];
    const float* Wv    = (const float*)d_in[9];
    const float* bv    = (const float*)d_in[10];
    const float* Wo    = (const float*)d_in[11];
    const float* bo    = (const float*)d_in[12];
    const float* W1    = (const float*)d_in[13];
    const float* b1    = (const float*)d_in[14];
    const float* W2    = (const float*)d_in[15];
    const float* b2    = (const float*)d_in[16];
    float* out = (float*)d_out;

    __half *h1, *qkv, *att, *h2, *ffn, *wpack, *woT, *w1T, *w2T;
    float *x2, *bpack;
    cudaGetSymbolAddress((void**)&h1,    g_h1);
    cudaGetSymbolAddress((void**)&qkv,   g_qkv);
    cudaGetSymbolAddress((void**)&att,   g_att);
    cudaGetSymbolAddress((void**)&x2,    g_x2);
    cudaGetSymbolAddress((void**)&h2,    g_h2);
    cudaGetSymbolAddress((void**)&ffn,   g_ffn);
    cudaGetSymbolAddress((void**)&wpack, g_wpack);
    cudaGetSymbolAddress((void**)&bpack, g_bpack);
    cudaGetSymbolAddress((void**)&woT,   g_woT);
    cudaGetSymbolAddress((void**)&w1T,   g_w1T);
    cudaGetSymbolAddress((void**)&w2T,   g_w2T);

    cudaFuncSetAttribute(hgemm_kernel<false,false,true>,  cudaFuncAttributeMaxDynamicSharedMemorySize, G_SMEM);
    cudaFuncSetAttribute(hgemm_kernel<false,true,false>,  cudaFuncAttributeMaxDynamicSharedMemorySize, G_SMEM);
    cudaFuncSetAttribute(hgemm_kernel<true,false,true>,   cudaFuncAttributeMaxDynamicSharedMemorySize, G_SMEM);
    cudaFuncSetAttribute(flash_h_kernel, cudaFuncAttributeMaxDynamicSharedMemorySize, FA_SMEM);

    pack_qkvT_kernel<<<(N3*Ck + 255)/256, 256>>>(Wq, Wk, Wv, bq, bk, bv);
    dim3 tb(32, 8);
    transpose_h_kernel<<<dim3(Ck/32, Ck/32), tb>>>(Wo, woT, Ck, Ck);
    transpose_h_kernel<<<dim3(FF/32, Ck/32), tb>>>(W1, w1T, Ck, FF);
    transpose_h_kernel<<<dim3(Ck/32, FF/32), tb>>>(W2, w2T, FF, Ck);

    dim3 lnb2(32, 8);
    ln_time_kernel<<<Bk*(Ck/32), lnb2>>>(x, ln1_g, ln1_b, h1);

    hgemm_kernel<false,false,true><<<dim3(N3/128, MROWS/128), 256, G_SMEM>>>(
        MROWS, N3, Ck, h1, wpack, bpack, (const float*)0, (float*)0, qkv);

    flash_h_kernel<<<Bk*Hk*(Tk/64), 128, FA_SMEM>>>(qkv, att);

    hgemm_kernel<false,true,false><<<dim3(Ck/128, MROWS/128), 256, G_SMEM>>>(
        MROWS, Ck, Ck, att, woT, bo, x, x2, (__half*)0);

    ln_time_kernel<<<Bk*(Ck/32), lnb2>>>(x2, ln2_g, ln2_b, h2);

    hgemm_kernel<true,false,true><<<dim3(FF/128, MROWS/128), 256, G_SMEM>>>(
        MROWS, FF, Ck, h2, w1T, b1, (const float*)0, (float*)0, ffn);

    hgemm_kernel<false,true,false><<<dim3(Ck/128, MROWS/128), 256, G_SMEM>>>(
        MROWS, Ck, FF, ffn, w2T, b2, x2, out, (__half*)0);
}

// round 11
// speedup vs baseline: 7.6224x; 1.0796x over previous
#include <cuda_runtime.h>
#include <cuda_fp16.h>
#include <math.h>
#include <stdint.h>

#define Bk 4
#define Tk 2048
#define Ck 1024
#define Hk 16
#define HSk 64
#define EPSk 1e-5f
#define MROWS (Bk*Tk)
#define N3 (3*Ck)
#define FF (4*Ck)

/* scratch (device globals; allocation is forbidden) */
__device__ __half g_h1[MROWS*Ck];
__device__ __half g_qkv[(size_t)MROWS*N3];
__device__ __half g_att[MROWS*Ck];
__device__ float  g_x2[MROWS*Ck];
__device__ __half g_h2[MROWS*Ck];
__device__ __half g_ffn[(size_t)MROWS*FF];
__device__ __half g_wpack[(size_t)N3*Ck];
__device__ float  g_bpack[N3];
__device__ __half g_woT[Ck*Ck];
__device__ __half g_w1T[(size_t)FF*Ck];
__device__ __half g_w2T[(size_t)Ck*FF];

/* ---------------- helpers ---------------- */
__device__ __forceinline__ void cp_async16(void* s, const void* g) {
    unsigned sa = (unsigned)__cvta_generic_to_shared(s);
    asm volatile("cp.async.cg.shared.global [%0], [%1], 16;" :: "r"(sa), "l"(g));
}
__device__ __forceinline__ void cp_commit() { asm volatile("cp.async.commit_group;"); }
__device__ __forceinline__ void cp_wait2() { asm volatile("cp.async.wait_group 2;" ::: "memory"); }
__device__ __forceinline__ void cp_wait1() { asm volatile("cp.async.wait_group 1;" ::: "memory"); }

__device__ __forceinline__ uint32_t smem_u32(const void* p) {
    return (uint32_t)__cvta_generic_to_shared(p);
}
__device__ __forceinline__ void mma16816(float* c, const unsigned* a, const unsigned* b) {
    asm volatile("mma.sync.aligned.m16n8k16.row.col.f32.f16.f16.f32 {%0,%1,%2,%3}, {%4,%5,%6,%7}, {%8,%9}, {%0,%1,%2,%3};"
        : "+f"(c[0]), "+f"(c[1]), "+f"(c[2]), "+f"(c[3])
        : "r"(a[0]), "r"(a[1]), "r"(a[2]), "r"(a[3]), "r"(b[0]), "r"(b[1]));
}
__device__ __forceinline__ void ldsm4(unsigned* r, uint32_t addr) {
    asm volatile("ldmatrix.sync.aligned.m8n8.x4.shared.b16 {%0,%1,%2,%3}, [%4];"
        : "=r"(r[0]), "=r"(r[1]), "=r"(r[2]), "=r"(r[3]) : "r"(addr));
}
__device__ __forceinline__ void ldsm4t(unsigned* r, uint32_t addr) {
    asm volatile("ldmatrix.sync.aligned.m8n8.x4.trans.shared.b16 {%0,%1,%2,%3}, [%4];"
        : "=r"(r[0]), "=r"(r[1]), "=r"(r[2]), "=r"(r[3]) : "r"(addr));
}

/* ---------------- LayerNorm over time axis, emits half --------------------- */
__global__ void ln_time_kernel(const float* __restrict__ x,
                               const float* __restrict__ gam,
                               const float* __restrict__ beta,
                               __half* __restrict__ out) {
    int cb = blockIdx.x % (Ck/32);
    int b  = blockIdx.x / (Ck/32);
    int tx = threadIdx.x, ty = threadIdx.y;
    int c  = cb*32 + tx;
    const float* xp = x + (size_t)b*Tk*Ck + c;
    float s = 0.f, s2 = 0.f;
    for (int t = ty; t < Tk; t += 8) {
        float v = xp[(size_t)t*Ck];
        s += v;
        s2 += v*v;
    }
    __shared__ float ss[8][32];
    __shared__ float ss2[8][32];
    ss[ty][tx] = s;
    ss2[ty][tx] = s2;
    __syncthreads();
    if (ty == 0) {
        for (int i = 1; i < 8; i++) { s += ss[i][tx]; s2 += ss2[i][tx]; }
        float m   = s / (float)Tk;
        float var = (s2 - (float)Tk*m*m) / (float)(Tk-1);
        float inv = rsqrtf(var + EPSk);
        ss[0][tx]  = m;
        ss2[0][tx] = inv;
    }
    __syncthreads();
    float m = ss[0][tx], inv = ss2[0][tx];
    float gg = gam[c], bb = beta[c];
    __half* op = out + (size_t)b*Tk*Ck + c;
    for (int t = ty; t < Tk; t += 8) {
        op[(size_t)t*Ck] = __float2half_rn(gg * (xp[(size_t)t*Ck] - m) * inv + bb);
    }
}

/* ---------------- pack qkv weights: K-major [3072][1024] half -------------- */
__global__ void pack_qkvT_kernel(const float* __restrict__ Wq, const float* __restrict__ Wk,
                                 const float* __restrict__ Wv, const float* __restrict__ bq,
                                 const float* __restrict__ bkk, const float* __restrict__ bv) {
    int i = blockIdx.x * blockDim.x + threadIdx.x;
    if (i < N3*Ck) {
        int n = i >> 10;
        int c = i & 1023;
        int which = n >> 10;
        int nl = n & 1023;
        int h = nl >> 6;
        int d = nl & 63;
        const float* W = (which == 0) ? Wq : ((which == 1) ? Wk : Wv);
        g_wpack[(size_t)n*Ck + c] = __float2half_rn(W[((size_t)h*Ck + c)*HSk + d]);
    }
    if (i < Ck) {
        g_bpack[i]        = bq[i];
        g_bpack[Ck + i]   = bkk[i];
        g_bpack[2*Ck + i] = bv[i];
    }
}

/* ---------------- tiled transpose: dst[n][k] = half(src[k][n]) ------------- */
__global__ void transpose_h_kernel(const float* __restrict__ src, __half* __restrict__ dst,
                                   int K, int N) {
    __shared__ float t[32][33];
    int k0 = blockIdx.y*32, n0 = blockIdx.x*32;
    int tx = threadIdx.x, ty = threadIdx.y;
    for (int i = 0; i < 4; i++) {
        t[ty + 8*i][tx] = src[(size_t)(k0 + ty + 8*i)*N + n0 + tx];
    }
    __syncthreads();
    for (int i = 0; i < 4; i++) {
        dst[(size_t)(n0 + ty + 8*i)*K + k0 + tx] = __float2half_rn(t[tx][ty + 8*i]);
    }
}

/* ---------------- fp16 tensor GEMM: C = A[M,K] x Bt[N,K]^T ----------------- */
/* 4-stage cp.async ring, ONE barrier per k-step, wait_group 2.               */
#define GP 40
#define GSTG (128*GP)
#define G_SMEM (4*2*GSTG*2)

template<bool RELU, bool RES, bool OHALF>
__global__ __launch_bounds__(256, 2)
void hgemm_kernel(int M, int N, int K,
                  const __half* __restrict__ A,
                  const __half* __restrict__ Bt,
                  const float* __restrict__ bias,
                  const float* __restrict__ res,
                  float* __restrict__ Cf,
                  __half* __restrict__ Ch) {
    extern __shared__ __half smh[];
    int tid  = threadIdx.x;
    int lane = tid & 31;
    int warp = tid >> 5;
    int g = lane >> 2;
    int c = lane & 3;
    int warpM = warp & 1;
    int warpN = warp >> 1;
    int bm0 = blockIdx.y * 128;
    int bn0 = blockIdx.x * 128;

    float acc[4][4][4];
    for (int mt = 0; mt < 4; mt++) {
        for (int nt = 0; nt < 4; nt++) {
            acc[mt][nt][0] = 0.f; acc[mt][nt][1] = 0.f;
            acc[mt][nt][2] = 0.f; acc[mt][nt][3] = 0.f;
        }
    }

    const __half* Ag = A  + (size_t)bm0 * K;
    const __half* Bg = Bt + (size_t)bn0 * K;
    int nk = K / 32;

    auto load_stage = [&](int st, int buf) {
        __half* As = smh + buf*2*GSTG;
        __half* Bs = As + GSTG;
        int k0 = st * 32;
        for (int i = 0; i < 2; i++) {
            int id = i*256 + tid;
            int row = id >> 2;
            int c8 = id & 3;
            cp_async16(As + row*GP + c8*8, Ag + (size_t)row*K + k0 + c8*8);
        }
        for (int i = 0; i < 2; i++) {
            int id = i*256 + tid;
            int row = id >> 2;
            int c8 = id & 3;
            cp_async16(Bs + row*GP + c8*8, Bg + (size_t)row*K + k0 + c8*8);
        }
    };

    load_stage(0, 0); cp_commit();
    load_stage(1, 1); cp_commit();

    int la = lane & 15;
    int lko = (lane >> 4) * 8;
    int lnb = (lane & 7) + ((lane & 16) >> 1);
    int lkb = lane & 8;

    for (int t = 0; t < nk; t++) {
        if (t + 2 < nk) { load_stage(t + 2, (t + 2) & 3); }
        cp_commit();
        cp_wait2();
        __syncthreads();
        const __half* As = smh + (t & 3)*2*GSTG;
        const __half* Bs = As + GSTG;
        for (int ks = 0; ks < 2; ks++) {
            int kc = ks * 16;
            unsigned af[4][4], bf[4][2];
            for (int mt = 0; mt < 4; mt++) {
                int r0 = warpM*64 + mt*16;
                ldsm4(af[mt], smem_u32(&As[(r0 + la)*GP + kc + lko]));
            }
            for (int pr = 0; pr < 2; pr++) {
                int n0 = warpN*32 + pr*16;
                unsigned rr[4];
                ldsm4(rr, smem_u32(&Bs[(n0 + lnb)*GP + kc + lkb]));
                bf[pr*2][0] = rr[0]; bf[pr*2][1] = rr[1];
                bf[pr*2+1][0] = rr[2]; bf[pr*2+1][1] = rr[3];
            }
            for (int mt = 0; mt < 4; mt++) {
                for (int nt = 0; nt < 4; nt++) {
                    mma16816(acc[mt][nt], af[mt], bf[nt]);
                }
            }
        }
    }

    for (int mt = 0; mt < 4; mt++) {
        for (int nt = 0; nt < 4; nt++) {
            for (int hh = 0; hh < 2; hh++) {
                int row = bm0 + warpM*64 + mt*16 + g + hh*8;
                int col = bn0 + warpN*32 + nt*8 + 2*c;
                float v0 = acc[mt][nt][hh*2+0] + bias[col];
                float v1 = acc[mt][nt][hh*2+1] + bias[col+1];
                if (RES) {
                    v0 += res[(size_t)row*N + col];
                    v1 += res[(size_t)row*N + col + 1];
                }
                if (RELU) { v0 = fmaxf(v0, 0.f); v1 = fmaxf(v1, 0.f); }
                if (OHALF) {
                    *(__half2*)&Ch[(size_t)row*N + col] = __floats2half2_rn(v0, v1);
                } else {
                    *(float2*)&Cf[(size_t)row*N + col] = make_float2(v0, v1);
                }
            }
        }
    }
}

/* ---------------- flash attention: 128-row Q tile, cp.async KV ring -------- */
#define FP 72
/* smem: Q/P 128 rows + 3 KV stages of (64 K rows + 64 V rows) */
#define FA_SMEM ((128*FP + 3*128*FP) * 2)

__global__ __launch_bounds__(256, 2)
void flash_h_kernel(const __half* __restrict__ qkv, __half* __restrict__ att) {
    extern __shared__ __half smh[];
    __half* Qs = smh;                 /* [128][FP], reused as Ps */
    __half* KV = smh + 128*FP;        /* 3 stages of [128][FP] (K rows 0-63, V rows 64-127) */
    __half* Ps = Qs;

    int tid  = threadIdx.x;
    int lane = tid & 31;
    int warp = tid >> 5;
    int gq = lane >> 2;
    int cq = lane & 3;

    const int ntiles = Tk / 128;      /* 16 */
    int qt = (ntiles - 1) - (blockIdx.x % ntiles);
    int h  = (blockIdx.x / ntiles) % Hk;
    int b  =  blockIdx.x / (ntiles * Hk);
    int q0 = qt * 128;
    const __half* qbase = qkv + (size_t)b*Tk*N3 + h*HSk;
    const __half* kbase = qbase + Ck;
    const __half* vbase = qbase + 2*Ck;

    /* stage Q: 128 rows x 64 halfs */
    for (int i = 0; i < 4; i++) {
        int id = i*256 + tid;
        int r = id >> 3;
        int c8 = id & 7;
        *(uint4*)&Qs[r*FP + c8*8] = *(const uint4*)(qbase + (size_t)(q0 + r)*N3 + c8*8);
    }
    __syncthreads();

    int la = lane & 15;
    int lko = (lane >> 4) * 8;
    int lnb = (lane & 7) + ((lane & 16) >> 1);
    int lkb = lane & 8;
    int ldo = (lane & 16) >> 1;

    int rl = warp*16 + gq;
    unsigned qa[4][4];
    for (int ks = 0; ks < 4; ks++) {
        ldsm4(qa[ks], smem_u32(&Qs[(warp*16 + la)*FP + ks*16 + lko]));
    }
    __syncthreads();   /* everyone has Q frags; Ps may now overwrite Qs */

    float m0 = -1e30f, m1 = -1e30f, l0 = 0.f, l1 = 0.f;
    float o[8][4];
    for (int nt = 0; nt < 8; nt++) {
        o[nt][0] = 0.f; o[nt][1] = 0.f; o[nt][2] = 0.f; o[nt][3] = 0.f;
    }

    int row0 = q0 + rl;
    int row1 = row0 + 8;
    int nkb = q0/64 + 2;

    /* KV stage loader: 64 K rows + 64 V rows, cp.async */
    auto stage_kv = [&](int kb, int buf) {
        __half* Kb = KV + buf*128*FP;
        __half* Vb = Kb + 64*FP;
        for (int i = 0; i < 2; i++) {
            int id = i*256 + tid;
            int r = id >> 3;
            int c8 = id & 7;
            cp_async16(&Kb[r*FP + c8*8], kbase + (size_t)(kb*64 + r)*N3 + c8*8);
            cp_async16(&Vb[r*FP + c8*8], vbase + (size_t)(kb*64 + r)*N3 + c8*8);
        }
    };

    stage_kv(0, 0); cp_commit();

    for (int kb = 0; kb < nkb; kb++) {
        if (kb + 1 < nkb) { stage_kv(kb + 1, (kb + 1) % 3); }
        cp_commit();
        cp_wait1();
        __syncthreads();
        const __half* Kb = KV + (kb % 3)*128*FP;
        const __half* Vb = Kb + 64*FP;

        /* S = Q K^T */
        float s[8][4];
        for (int nt = 0; nt < 8; nt++) {
            s[nt][0] = 0.f; s[nt][1] = 0.f; s[nt][2] = 0.f; s[nt][3] = 0.f;
        }
        for (int ks = 0; ks < 4; ks++) {
            int kc = ks*16;
            unsigned bf[8][2];
            for (int pr = 0; pr < 4; pr++) {
                unsigned rr[4];
                ldsm4(rr, smem_u32(&Kb[(pr*16 + lnb)*FP + kc + lkb]));
                bf[pr*2][0] = rr[0]; bf[pr*2][1] = rr[1];
                bf[pr*2+1][0] = rr[2]; bf[pr*2+1][1] = rr[3];
            }
            for (int nt = 0; nt < 8; nt++) {
                mma16816(s[nt], qa[ks], bf[nt]);
            }
        }

        /* scale (+mask only when block touches diagonal), online softmax */
        float rmax0 = -1e30f, rmax1 = -1e30f;
        if (kb*64 + 63 <= row0) {
            for (int nt = 0; nt < 8; nt++) {
                s[nt][0] *= 0.03125f; s[nt][1] *= 0.03125f;
                s[nt][2] *= 0.03125f; s[nt][3] *= 0.03125f;
                rmax0 = fmaxf(rmax0, fmaxf(s[nt][0], s[nt][1]));
                rmax1 = fmaxf(rmax1, fmaxf(s[nt][2], s[nt][3]));
            }
        } else {
            for (int nt = 0; nt < 8; nt++) {
                int col = kb*64 + nt*8 + 2*cq;
                s[nt][0] = (col   <= row0) ? s[nt][0]*0.03125f : -1e30f;
                s[nt][1] = (col+1 <= row0) ? s[nt][1]*0.03125f : -1e30f;
                s[nt][2] = (col   <= row1) ? s[nt][2]*0.03125f : -1e30f;
                s[nt][3] = (col+1 <= row1) ? s[nt][3]*0.03125f : -1e30f;
                rmax0 = fmaxf(rmax0, fmaxf(s[nt][0], s[nt][1]));
                rmax1 = fmaxf(rmax1, fmaxf(s[nt][2], s[nt][3]));
            }
        }
        rmax0 = fmaxf(rmax0, __shfl_xor_sync(0xffffffffu, rmax0, 1));
        rmax0 = fmaxf(rmax0, __shfl_xor_sync(0xffffffffu, rmax0, 2));
        rmax1 = fmaxf(rmax1, __shfl_xor_sync(0xffffffffu, rmax1, 1));
        rmax1 = fmaxf(rmax1, __shfl_xor_sync(0xffffffffu, rmax1, 2));
        float mn0 = fmaxf(m0, rmax0);
        float mn1 = fmaxf(m1, rmax1);
        float corr0 = __expf(m0 - mn0);
        float corr1 = __expf(m1 - mn1);
        float ps0 = 0.f, ps1 = 0.f;
        for (int nt = 0; nt < 8; nt++) {
            float p0 = __expf(s[nt][0] - mn0);
            float p1 = __expf(s[nt][1] - mn0);
            float p2 = __expf(s[nt][2] - mn1);
            float p3 = __expf(s[nt][3] - mn1);
            ps0 += p0 + p1;
            ps1 += p2 + p3;
            int cl = nt*8 + 2*cq;
            *(__half2*)&Ps[rl*FP + cl]     = __floats2half2_rn(p0, p1);
            *(__half2*)&Ps[(rl+8)*FP + cl] = __floats2half2_rn(p2, p3);
        }
        ps0 += __shfl_xor_sync(0xffffffffu, ps0, 1);
        ps0 += __shfl_xor_sync(0xffffffffu, ps0, 2);
        ps1 += __shfl_xor_sync(0xffffffffu, ps1, 1);
        ps1 += __shfl_xor_sync(0xffffffffu, ps1, 2);
        l0 = l0*corr0 + ps0;
        l1 = l1*corr1 + ps1;
        m0 = mn0;
        m1 = mn1;
        for (int nt = 0; nt < 8; nt++) {
            o[nt][0] *= corr0; o[nt][1] *= corr0;
            o[nt][2] *= corr1; o[nt][3] *= corr1;
        }
        __syncwarp();

        /* O += P V */
        for (int ks = 0; ks < 4; ks++) {
            int kc = ks*16;
            unsigned pa[4];
            ldsm4(pa, smem_u32(&Ps[(warp*16 + la)*FP + kc + lko]));
            for (int pr = 0; pr < 4; pr++) {
                unsigned rr[4];
                ldsm4t(rr, smem_u32(&Vb[(kc + la)*FP + pr*16 + ldo]));
                mma16816(o[pr*2],     pa, rr + 0);
                mma16816(o[pr*2 + 1], pa, rr + 2);
            }
        }
    }

    float inv0 = 1.f / l0;
    float inv1 = 1.f / l1;
    __half* ob0 = att + (size_t)(b*Tk + row0)*Ck + h*HSk;
    __half* ob1 = att + (size_t)(b*Tk + row1)*Ck + h*HSk;
    for (int nt = 0; nt < 8; nt++) {
        int cl = nt*8 + 2*cq;
        *(__half2*)&ob0[cl] = __floats2half2_rn(o[nt][0]*inv0, o[nt][1]*inv0);
        *(__half2*)&ob1[cl] = __floats2half2_rn(o[nt][2]*inv1, o[nt][3]*inv1);
    }
}

/* --------------------------------------------------------------------------- */
extern "C" void kernel_launch(void* const* d_in, const int* in_sizes, int n_in,
                              void* d_out, int out_size) {
    const float* x     = (const float*)d_in[0];
    const float* ln1_g = (const float*)d_in[1];
    const float* ln1_b = (const float*)d_in[2];
    const float* ln2_g = (const float*)d_in[3];
    const float* ln2_b = (const float*)d_in[4];
    const float* Wq    = (const float*)d_in[5];
    const float* bq    = (const float*)d_in[6];
    const float* Wk    = (const float*)d_in[7];
    const float* bk    = (const float*)d_in[8];
    const float* Wv    = (const float*)d_in[9];
    const float* bv    = (const float*)d_in[10];
    const float* Wo    = (const float*)d_in[11];
    const float* bo    = (const float*)d_in[12];
    const float* W1    = (const float*)d_in[13];
    const float* b1    = (const float*)d_in[14];
    const float* W2    = (const float*)d_in[15];
    const float* b2    = (const float*)d_in[16];
    float* out = (float*)d_out;

    __half *h1, *qkv, *att, *h2, *ffn, *wpack, *woT, *w1T, *w2T;
    float *x2, *bpack;
    cudaGetSymbolAddress((void**)&h1,    g_h1);
    cudaGetSymbolAddress((void**)&qkv,   g_qkv);
    cudaGetSymbolAddress((void**)&att,   g_att);
    cudaGetSymbolAddress((void**)&x2,    g_x2);
    cudaGetSymbolAddress((void**)&h2,    g_h2);
    cudaGetSymbolAddress((void**)&ffn,   g_ffn);
    cudaGetSymbolAddress((void**)&wpack, g_wpack);
    cudaGetSymbolAddress((void**)&bpack, g_bpack);
    cudaGetSymbolAddress((void**)&woT,   g_woT);
    cudaGetSymbolAddress((void**)&w1T,   g_w1T);
    cudaGetSymbolAddress((void**)&w2T,   g_w2T);

    cudaFuncSetAttribute(hgemm_kernel<false,false,true>,  cudaFuncAttributeMaxDynamicSharedMemorySize, G_SMEM);
    cudaFuncSetAttribute(hgemm_kernel<false,true,false>,  cudaFuncAttributeMaxDynamicSharedMemorySize, G_SMEM);
    cudaFuncSetAttribute(hgemm_kernel<true,false,true>,   cudaFuncAttributeMaxDynamicSharedMemorySize, G_SMEM);
    cudaFuncSetAttribute(flash_h_kernel, cudaFuncAttributeMaxDynamicSharedMemorySize, FA_SMEM);

    pack_qkvT_kernel<<<(N3*Ck + 255)/256, 256>>>(Wq, Wk, Wv, bq, bk, bv);
    dim3 tb(32, 8);
    transpose_h_kernel<<<dim3(Ck/32, Ck/32), tb>>>(Wo, woT, Ck, Ck);
    transpose_h_kernel<<<dim3(FF/32, Ck/32), tb>>>(W1, w1T, Ck, FF);
    transpose_h_kernel<<<dim3(Ck/32, FF/32), tb>>>(W2, w2T, FF, Ck);

    dim3 lnb2(32, 8);
    ln_time_kernel<<<Bk*(Ck/32), lnb2>>>(x, ln1_g, ln1_b, h1);

    hgemm_kernel<false,false,true><<<dim3(N3/128, MROWS/128), 256, G_SMEM>>>(
        MROWS, N3, Ck, h1, wpack, bpack, (const float*)0, (float*)0, qkv);

    flash_h_kernel<<<Bk*Hk*(Tk/128), 256, FA_SMEM>>>(qkv, att);

    hgemm_kernel<false,true,false><<<dim3(Ck/128, MROWS/128), 256, G_SMEM>>>(
        MROWS, Ck, Ck, att, woT, bo, x, x2, (__half*)0);

    ln_time_kernel<<<Bk*(Ck/32), lnb2>>>(x2, ln2_g, ln2_b, h2);

    hgemm_kernel<true,false,true><<<dim3(FF/128, MROWS/128), 256, G_SMEM>>>(
        MROWS, FF, Ck, h2, w1T, b1, (const float*)0, (float*)0, ffn);

    hgemm_kernel<false,true,false><<<dim3(Ck/128, MROWS/128), 256, G_SMEM>>>(
        MROWS, Ck, FF, ffn, w2T, b2, x2, out, (__half*)0);
}

// round 16
// speedup vs baseline: 8.5491x; 1.1216x over previous
#include <cuda_runtime.h>
#include <cuda_fp16.h>
#include <math.h>
#include <stdint.h>

#define Bk 4
#define Tk 2048
#define Ck 1024
#define Hk 16
#define HSk 64
#define EPSk 1e-5f
#define MROWS (Bk*Tk)
#define N3 (3*Ck)
#define FF (4*Ck)

/* scratch (device globals; allocation is forbidden) */
__device__ __half g_h1[MROWS*Ck];
__device__ __half g_qkv[(size_t)MROWS*N3];
__device__ __half g_att[MROWS*Ck];
__device__ float  g_x2[MROWS*Ck];
__device__ __half g_h2[MROWS*Ck];
__device__ __half g_ffn[(size_t)MROWS*FF];
__device__ __half g_wpack[(size_t)N3*Ck];
__device__ float  g_bpack[N3];
__device__ __half g_woT[Ck*Ck];
__device__ __half g_w1T[(size_t)FF*Ck];
__device__ __half g_w2T[(size_t)Ck*FF];

/* ---------------- helpers ---------------- */
__device__ __forceinline__ void cp_async16(void* s, const void* g) {
    unsigned sa = (unsigned)__cvta_generic_to_shared(s);
    asm volatile("cp.async.cg.shared.global [%0], [%1], 16;" :: "r"(sa), "l"(g));
}
__device__ __forceinline__ void cp_commit() { asm volatile("cp.async.commit_group;"); }
__device__ __forceinline__ void cp_wait2() { asm volatile("cp.async.wait_group 2;" ::: "memory"); }
__device__ __forceinline__ void cp_wait1() { asm volatile("cp.async.wait_group 1;" ::: "memory"); }

__device__ __forceinline__ uint32_t smem_u32(const void* p) {
    return (uint32_t)__cvta_generic_to_shared(p);
}
__device__ __forceinline__ void mma16816(float* c, const unsigned* a, const unsigned* b) {
    asm volatile("mma.sync.aligned.m16n8k16.row.col.f32.f16.f16.f32 {%0,%1,%2,%3}, {%4,%5,%6,%7}, {%8,%9}, {%0,%1,%2,%3};"
        : "+f"(c[0]), "+f"(c[1]), "+f"(c[2]), "+f"(c[3])
        : "r"(a[0]), "r"(a[1]), "r"(a[2]), "r"(a[3]), "r"(b[0]), "r"(b[1]));
}
__device__ __forceinline__ void ldsm4(unsigned* r, uint32_t addr) {
    asm volatile("ldmatrix.sync.aligned.m8n8.x4.shared.b16 {%0,%1,%2,%3}, [%4];"
        : "=r"(r[0]), "=r"(r[1]), "=r"(r[2]), "=r"(r[3]) : "r"(addr));
}
__device__ __forceinline__ void ldsm4t(unsigned* r, uint32_t addr) {
    asm volatile("ldmatrix.sync.aligned.m8n8.x4.trans.shared.b16 {%0,%1,%2,%3}, [%4];"
        : "=r"(r[0]), "=r"(r[1]), "=r"(r[2]), "=r"(r[3]) : "r"(addr));
}

/* ---------------- LayerNorm over time axis, emits half --------------------- */
__global__ void ln_time_kernel(const float* __restrict__ x,
                               const float* __restrict__ gam,
                               const float* __restrict__ beta,
                               __half* __restrict__ out) {
    int cb = blockIdx.x % (Ck/32);
    int b  = blockIdx.x / (Ck/32);
    int tx = threadIdx.x, ty = threadIdx.y;
    int c  = cb*32 + tx;
    const float* xp = x + (size_t)b*Tk*Ck + c;
    float s = 0.f, s2 = 0.f;
    for (int t = ty; t < Tk; t += 8) {
        float v = xp[(size_t)t*Ck];
        s += v;
        s2 += v*v;
    }
    __shared__ float ss[8][32];
    __shared__ float ss2[8][32];
    ss[ty][tx] = s;
    ss2[ty][tx] = s2;
    __syncthreads();
    if (ty == 0) {
        for (int i = 1; i < 8; i++) { s += ss[i][tx]; s2 += ss2[i][tx]; }
        float m   = s / (float)Tk;
        float var = (s2 - (float)Tk*m*m) / (float)(Tk-1);
        float inv = rsqrtf(var + EPSk);
        ss[0][tx]  = m;
        ss2[0][tx] = inv;
    }
    __syncthreads();
    float m = ss[0][tx], inv = ss2[0][tx];
    float gg = gam[c], bb = beta[c];
    __half* op = out + (size_t)b*Tk*Ck + c;
    for (int t = ty; t < Tk; t += 8) {
        op[(size_t)t*Ck] = __float2half_rn(gg * (xp[(size_t)t*Ck] - m) * inv + bb);
    }
}

/* ---------------- pack qkv weights: K-major [3072][1024] half -------------- */
__global__ void pack_qkvT_kernel(const float* __restrict__ Wq, const float* __restrict__ Wk,
                                 const float* __restrict__ Wv, const float* __restrict__ bq,
                                 const float* __restrict__ bkk, const float* __restrict__ bv) {
    int i = blockIdx.x * blockDim.x + threadIdx.x;
    if (i < N3*Ck) {
        int n = i >> 10;
        int c = i & 1023;
        int which = n >> 10;
        int nl = n & 1023;
        int h = nl >> 6;
        int d = nl & 63;
        const float* W = (which == 0) ? Wq : ((which == 1) ? Wk : Wv);
        g_wpack[(size_t)n*Ck + c] = __float2half_rn(W[((size_t)h*Ck + c)*HSk + d]);
    }
    if (i < Ck) {
        g_bpack[i]        = bq[i];
        g_bpack[Ck + i]   = bkk[i];
        g_bpack[2*Ck + i] = bv[i];
    }
}

/* ---------------- tiled transpose: dst[n][k] = half(src[k][n]) ------------- */
__global__ void transpose_h_kernel(const float* __restrict__ src, __half* __restrict__ dst,
                                   int K, int N) {
    __shared__ float t[32][33];
    int k0 = blockIdx.y*32, n0 = blockIdx.x*32;
    int tx = threadIdx.x, ty = threadIdx.y;
    for (int i = 0; i < 4; i++) {
        t[ty + 8*i][tx] = src[(size_t)(k0 + ty + 8*i)*N + n0 + tx];
    }
    __syncthreads();
    for (int i = 0; i < 4; i++) {
        dst[(size_t)(n0 + ty + 8*i)*K + k0 + tx] = __float2half_rn(t[tx][ty + 8*i]);
    }
}

/* ---------------- fp16 tensor GEMM: C = A[M,K] x Bt[N,K]^T ----------------- */
/* 128x128 block, 4 warps (warp tile 64x64), 4-stage ring, 1 barrier/k-step. */
#define GP 40
#define GSTG (128*GP)
#define G_SMEM (4*2*GSTG*2)

template<bool RELU, bool RES, bool OHALF>
__global__ __launch_bounds__(128, 2)
void hgemm_kernel(int M, int N, int K,
                  const __half* __restrict__ A,
                  const __half* __restrict__ Bt,
                  const float* __restrict__ bias,
                  const float* __restrict__ res,
                  float* __restrict__ Cf,
                  __half* __restrict__ Ch) {
    extern __shared__ __half smh[];
    int tid  = threadIdx.x;
    int lane = tid & 31;
    int warp = tid >> 5;
    int g = lane >> 2;
    int c = lane & 3;
    int warpM = warp & 1;
    int warpN = warp >> 1;
    int bm0 = blockIdx.y * 128;
    int bn0 = blockIdx.x * 128;

    float acc[4][8][4];
    for (int mt = 0; mt < 4; mt++) {
        for (int nt = 0; nt < 8; nt++) {
            acc[mt][nt][0] = 0.f; acc[mt][nt][1] = 0.f;
            acc[mt][nt][2] = 0.f; acc[mt][nt][3] = 0.f;
        }
    }

    const __half* Ag = A  + (size_t)bm0 * K;
    const __half* Bg = Bt + (size_t)bn0 * K;
    int nk = K / 32;

    auto load_stage = [&](int st, int buf) {
        __half* As = smh + buf*2*GSTG;
        __half* Bs = As + GSTG;
        int k0 = st * 32;
        for (int i = 0; i < 4; i++) {
            int id = i*128 + tid;
            int row = id >> 2;
            int c8 = id & 3;
            cp_async16(As + row*GP + c8*8, Ag + (size_t)row*K + k0 + c8*8);
        }
        for (int i = 0; i < 4; i++) {
            int id = i*128 + tid;
            int row = id >> 2;
            int c8 = id & 3;
            cp_async16(Bs + row*GP + c8*8, Bg + (size_t)row*K + k0 + c8*8);
        }
    };

    load_stage(0, 0); cp_commit();
    load_stage(1, 1); cp_commit();

    int la = lane & 15;
    int lko = (lane >> 4) * 8;
    int lnb = (lane & 7) + ((lane & 16) >> 1);
    int lkb = lane & 8;

    for (int t = 0; t < nk; t++) {
        if (t + 2 < nk) { load_stage(t + 2, (t + 2) & 3); }
        cp_commit();
        cp_wait2();
        __syncthreads();
        const __half* As = smh + (t & 3)*2*GSTG;
        const __half* Bs = As + GSTG;
        for (int ks = 0; ks < 2; ks++) {
            int kc = ks * 16;
            unsigned af[4][4], bf[8][2];
            for (int mt = 0; mt < 4; mt++) {
                int r0 = warpM*64 + mt*16;
                ldsm4(af[mt], smem_u32(&As[(r0 + la)*GP + kc + lko]));
            }
            for (int pr = 0; pr < 4; pr++) {
                int n0 = warpN*64 + pr*16;
                unsigned rr[4];
                ldsm4(rr, smem_u32(&Bs[(n0 + lnb)*GP + kc + lkb]));
                bf[pr*2][0] = rr[0]; bf[pr*2][1] = rr[1];
                bf[pr*2+1][0] = rr[2]; bf[pr*2+1][1] = rr[3];
            }
            for (int mt = 0; mt < 4; mt++) {
                for (int nt = 0; nt < 8; nt++) {
                    mma16816(acc[mt][nt], af[mt], bf[nt]);
                }
            }
        }
    }

    for (int mt = 0; mt < 4; mt++) {
        for (int nt = 0; nt < 8; nt++) {
            for (int hh = 0; hh < 2; hh++) {
                int row = bm0 + warpM*64 + mt*16 + g + hh*8;
                int col = bn0 + warpN*64 + nt*8 + 2*c;
                float v0 = acc[mt][nt][hh*2+0] + bias[col];
                float v1 = acc[mt][nt][hh*2+1] + bias[col+1];
                if (RES) {
                    v0 += res[(size_t)row*N + col];
                    v1 += res[(size_t)row*N + col + 1];
                }
                if (RELU) { v0 = fmaxf(v0, 0.f); v1 = fmaxf(v1, 0.f); }
                if (OHALF) {
                    *(__half2*)&Ch[(size_t)row*N + col] = __floats2half2_rn(v0, v1);
                } else {
                    *(float2*)&Cf[(size_t)row*N + col] = make_float2(v0, v1);
                }
            }
        }
    }
}

/* ---------------- flash attention: 128-row Q tile, cp.async KV ring -------- */
#define FP 72
#define FA_SMEM ((128*FP + 3*128*FP) * 2)

__global__ __launch_bounds__(256, 2)
void flash_h_kernel(const __half* __restrict__ qkv, __half* __restrict__ att) {
    extern __shared__ __half smh[];
    __half* Qs = smh;
    __half* KV = smh + 128*FP;
    __half* Ps = Qs;

    int tid  = threadIdx.x;
    int lane = tid & 31;
    int warp = tid >> 5;
    int gq = lane >> 2;
    int cq = lane & 3;

    const int ntiles = Tk / 128;
    int qt = (ntiles - 1) - (blockIdx.x % ntiles);
    int h  = (blockIdx.x / ntiles) % Hk;
    int b  =  blockIdx.x / (ntiles * Hk);
    int q0 = qt * 128;
    const __half* qbase = qkv + (size_t)b*Tk*N3 + h*HSk;
    const __half* kbase = qbase + Ck;
    const __half* vbase = qbase + 2*Ck;

    for (int i = 0; i < 4; i++) {
        int id = i*256 + tid;
        int r = id >> 3;
        int c8 = id & 7;
        *(uint4*)&Qs[r*FP + c8*8] = *(const uint4*)(qbase + (size_t)(q0 + r)*N3 + c8*8);
    }
    __syncthreads();

    int la = lane & 15;
    int lko = (lane >> 4) * 8;
    int lnb = (lane & 7) + ((lane & 16) >> 1);
    int lkb = lane & 8;
    int ldo = (lane & 16) >> 1;

    int rl = warp*16 + gq;
    unsigned qa[4][4];
    for (int ks = 0; ks < 4; ks++) {
        ldsm4(qa[ks], smem_u32(&Qs[(warp*16 + la)*FP + ks*16 + lko]));
    }
    __syncthreads();

    float m0 = -1e30f, m1 = -1e30f, l0 = 0.f, l1 = 0.f;
    float o[8][4];
    for (int nt = 0; nt < 8; nt++) {
        o[nt][0] = 0.f; o[nt][1] = 0.f; o[nt][2] = 0.f; o[nt][3] = 0.f;
    }

    int row0 = q0 + rl;
    int row1 = row0 + 8;
    int nkb = q0/64 + 2;

    auto stage_kv = [&](int kb, int buf) {
        __half* Kb = KV + buf*128*FP;
        __half* Vb = Kb + 64*FP;
        for (int i = 0; i < 2; i++) {
            int id = i*256 + tid;
            int r = id >> 3;
            int c8 = id & 7;
            cp_async16(&Kb[r*FP + c8*8], kbase + (size_t)(kb*64 + r)*N3 + c8*8);
            cp_async16(&Vb[r*FP + c8*8], vbase + (size_t)(kb*64 + r)*N3 + c8*8);
        }
    };

    stage_kv(0, 0); cp_commit();

    for (int kb = 0; kb < nkb; kb++) {
        if (kb + 1 < nkb) { stage_kv(kb + 1, (kb + 1) % 3); }
        cp_commit();
        cp_wait1();
        __syncthreads();
        const __half* Kb = KV + (kb % 3)*128*FP;
        const __half* Vb = Kb + 64*FP;

        float s[8][4];
        for (int nt = 0; nt < 8; nt++) {
            s[nt][0] = 0.f; s[nt][1] = 0.f; s[nt][2] = 0.f; s[nt][3] = 0.f;
        }
        for (int ks = 0; ks < 4; ks++) {
            int kc = ks*16;
            unsigned bf[8][2];
            for (int pr = 0; pr < 4; pr++) {
                unsigned rr[4];
                ldsm4(rr, smem_u32(&Kb[(pr*16 + lnb)*FP + kc + lkb]));
                bf[pr*2][0] = rr[0]; bf[pr*2][1] = rr[1];
                bf[pr*2+1][0] = rr[2]; bf[pr*2+1][1] = rr[3];
            }
            for (int nt = 0; nt < 8; nt++) {
                mma16816(s[nt], qa[ks], bf[nt]);
            }
        }

        float rmax0 = -1e30f, rmax1 = -1e30f;
        if (kb*64 + 63 <= row0) {
            for (int nt = 0; nt < 8; nt++) {
                s[nt][0] *= 0.03125f; s[nt][1] *= 0.03125f;
                s[nt][2] *= 0.03125f; s[nt][3] *= 0.03125f;
                rmax0 = fmaxf(rmax0, fmaxf(s[nt][0], s[nt][1]));
                rmax1 = fmaxf(rmax1, fmaxf(s[nt][2], s[nt][3]));
            }
        } else {
            for (int nt = 0; nt < 8; nt++) {
                int col = kb*64 + nt*8 + 2*cq;
                s[nt][0] = (col   <= row0) ? s[nt][0]*0.03125f : -1e30f;
                s[nt][1] = (col+1 <= row0) ? s[nt][1]*0.03125f : -1e30f;
                s[nt][2] = (col   <= row1) ? s[nt][2]*0.03125f : -1e30f;
                s[nt][3] = (col+1 <= row1) ? s[nt][3]*0.03125f : -1e30f;
                rmax0 = fmaxf(rmax0, fmaxf(s[nt][0], s[nt][1]));
                rmax1 = fmaxf(rmax1, fmaxf(s[nt][2], s[nt][3]));
            }
        }
        rmax0 = fmaxf(rmax0, __shfl_xor_sync(0xffffffffu, rmax0, 1));
        rmax0 = fmaxf(rmax0, __shfl_xor_sync(0xffffffffu, rmax0, 2));
        rmax1 = fmaxf(rmax1, __shfl_xor_sync(0xffffffffu, rmax1, 1));
        rmax1 = fmaxf(rmax1, __shfl_xor_sync(0xffffffffu, rmax1, 2));
        float mn0 = fmaxf(m0, rmax0);
        float mn1 = fmaxf(m1, rmax1);
        float corr0 = __expf(m0 - mn0);
        float corr1 = __expf(m1 - mn1);
        float ps0 = 0.f, ps1 = 0.f;
        for (int nt = 0; nt < 8; nt++) {
            float p0 = __expf(s[nt][0] - mn0);
            float p1 = __expf(s[nt][1] - mn0);
            float p2 = __expf(s[nt][2] - mn1);
            float p3 = __expf(s[nt][3] - mn1);
            ps0 += p0 + p1;
            ps1 += p2 + p3;
            int cl = nt*8 + 2*cq;
            *(__half2*)&Ps[rl*FP + cl]     = __floats2half2_rn(p0, p1);
            *(__half2*)&Ps[(rl+8)*FP + cl] = __floats2half2_rn(p2, p3);
        }
        ps0 += __shfl_xor_sync(0xffffffffu, ps0, 1);
        ps0 += __shfl_xor_sync(0xffffffffu, ps0, 2);
        ps1 += __shfl_xor_sync(0xffffffffu, ps1, 1);
        ps1 += __shfl_xor_sync(0xffffffffu, ps1, 2);
        l0 = l0*corr0 + ps0;
        l1 = l1*corr1 + ps1;
        m0 = mn0;
        m1 = mn1;
        for (int nt = 0; nt < 8; nt++) {
            o[nt][0] *= corr0; o[nt][1] *= corr0;
            o[nt][2] *= corr1; o[nt][3] *= corr1;
        }
        __syncwarp();

        for (int ks = 0; ks < 4; ks++) {
            int kc = ks*16;
            unsigned pa[4];
            ldsm4(pa, smem_u32(&Ps[(warp*16 + la)*FP + kc + lko]));
            for (int pr = 0; pr < 4; pr++) {
                unsigned rr[4];
                ldsm4t(rr, smem_u32(&Vb[(kc + la)*FP + pr*16 + ldo]));
                mma16816(o[pr*2],     pa, rr + 0);
                mma16816(o[pr*2 + 1], pa, rr + 2);
            }
        }
    }

    float inv0 = 1.f / l0;
    float inv1 = 1.f / l1;
    __half* ob0 = att + (size_t)(b*Tk + row0)*Ck + h*HSk;
    __half* ob1 = att + (size_t)(b*Tk + row1)*Ck + h*HSk;
    for (int nt = 0; nt < 8; nt++) {
        int cl = nt*8 + 2*cq;
        *(__half2*)&ob0[cl] = __floats2half2_rn(o[nt][0]*inv0, o[nt][1]*inv0);
        *(__half2*)&ob1[cl] = __floats2half2_rn(o[nt][2]*inv1, o[nt][3]*inv1);
    }
}

/* --------------------------------------------------------------------------- */
extern "C" void kernel_launch(void* const* d_in, const int* in_sizes, int n_in,
                              void* d_out, int out_size) {
    const float* x     = (const float*)d_in[0];
    const float* ln1_g = (const float*)d_in[1];
    const float* ln1_b = (const float*)d_in[2];
    const float* ln2_g = (const float*)d_in[3];
    const float* ln2_b = (const float*)d_in[4];
    const float* Wq    = (const float*)d_in[5];
    const float* bq    = (const float*)d_in[6];
    const float* Wk    = (const float*)d_in[7];
    const float* bk    = (const float*)d_in[8];
    const float* Wv    = (const float*)d_in[9];
    const float* bv    = (const float*)d_in[10];
    const float* Wo    = (const float*)d_in[11];
    const float* bo    = (const float*)d_in[12];
    const float* W1    = (const float*)d_in[13];
    const float* b1    = (const float*)d_in[14];
    const float* W2    = (const float*)d_in[15];
    const float* b2    = (const float*)d_in[16];
    float* out = (float*)d_out;

    __half *h1, *qkv, *att, *h2, *ffn, *wpack, *woT, *w1T, *w2T;
    float *x2, *bpack;
    cudaGetSymbolAddress((void**)&h1,    g_h1);
    cudaGetSymbolAddress((void**)&qkv,   g_qkv);
    cudaGetSymbolAddress((void**)&att,   g_att);
    cudaGetSymbolAddress((void**)&x2,    g_x2);
    cudaGetSymbolAddress((void**)&h2,    g_h2);
    cudaGetSymbolAddress((void**)&ffn,   g_ffn);
    cudaGetSymbolAddress((void**)&wpack, g_wpack);
    cudaGetSymbolAddress((void**)&bpack, g_bpack);
    cudaGetSymbolAddress((void**)&woT,   g_woT);
    cudaGetSymbolAddress((void**)&w1T,   g_w1T);
    cudaGetSymbolAddress((void**)&w2T,   g_w2T);

    cudaFuncSetAttribute(hgemm_kernel<false,false,true>,  cudaFuncAttributeMaxDynamicSharedMemorySize, G_SMEM);
    cudaFuncSetAttribute(hgemm_kernel<false,true,false>,  cudaFuncAttributeMaxDynamicSharedMemorySize, G_SMEM);
    cudaFuncSetAttribute(hgemm_kernel<true,false,true>,   cudaFuncAttributeMaxDynamicSharedMemorySize, G_SMEM);
    cudaFuncSetAttribute(flash_h_kernel, cudaFuncAttributeMaxDynamicSharedMemorySize, FA_SMEM);

    pack_qkvT_kernel<<<(N3*Ck + 255)/256, 256>>>(Wq, Wk, Wv, bq, bk, bv);
    dim3 tb(32, 8);
    transpose_h_kernel<<<dim3(Ck/32, Ck/32), tb>>>(Wo, woT, Ck, Ck);
    transpose_h_kernel<<<dim3(FF/32, Ck/32), tb>>>(W1, w1T, Ck, FF);
    transpose_h_kernel<<<dim3(Ck/32, FF/32), tb>>>(W2, w2T, FF, Ck);

    dim3 lnb2(32, 8);
    ln_time_kernel<<<Bk*(Ck/32), lnb2>>>(x, ln1_g, ln1_b, h1);

    hgemm_kernel<false,false,true><<<dim3(N3/128, MROWS/128), 128, G_SMEM>>>(
        MROWS, N3, Ck, h1, wpack, bpack, (const float*)0, (float*)0, qkv);

    flash_h_kernel<<<Bk*Hk*(Tk/128), 256, FA_SMEM>>>(qkv, att);

    hgemm_kernel<false,true,false><<<dim3(Ck/128, MROWS/128), 128, G_SMEM>>>(
        MROWS, Ck, Ck, att, woT, bo, x, x2, (__half*)0);

    ln_time_kernel<<<Bk*(Ck/32), lnb2>>>(x2, ln2_g, ln2_b, h2);

    hgemm_kernel<true,false,true><<<dim3(FF/128, MROWS/128), 128, G_SMEM>>>(
        MROWS, FF, Ck, h2, w1T, b1, (const float*)0, (float*)0, ffn);

    hgemm_kernel<false,true,false><<<dim3(Ck/128, MROWS/128), 128, G_SMEM>>>(
        MROWS, Ck, FF, ffn, w2T, b2, x2, out, (__half*)0);
}